// round 2
// baseline (speedup 1.0000x reference)
#include <cuda_runtime.h>
#include <math.h>
#include <stdint.h>

#define N_TOT   131072
#define C_DIM   512
#define H_NUM   8
#define K_PATCH 128
#define HD_DIM  64
#define P_NUM   1024          // N_TOT / K_PATCH
#define C3      1536          // 3 * C_DIM
#define RPE_MAX 33            // smem capacity; actual rpe_num passed at runtime

// Scratch (device globals: allowed; no cudaMalloc anywhere)
static __device__ float g_qkv[(size_t)N_TOT * C3];    // 805 MB
static __device__ float g_ao [(size_t)N_TOT * C_DIM]; // 268 MB

// ---------------------------------------------------------------------------
// GEMM (NT):  out[row(m), j] = sum_c A[arow(m), c] * W[j, c] + bias[j]
//   arow(m) = gidx ? gidx[m] : m      (gather)
//   row(m)  = sidx ? sidx[m] : m      (scatter)
// BM=BN=64, BK=16, 256 threads, 4x4 microtile.
// ---------------------------------------------------------------------------
__global__ __launch_bounds__(256) void gemm_nt(
    const float* __restrict__ A, const float* __restrict__ W,
    const float* __restrict__ bias, float* __restrict__ out,
    const int* __restrict__ gidx, const int* __restrict__ sidx,
    int Ncols, int Kd)
{
    __shared__ __align__(16) float As[16][64];
    __shared__ __align__(16) float Ws[16][64];

    const int m0 = blockIdx.y * 64;
    const int j0 = blockIdx.x * 64;
    const int t  = threadIdx.x;
    const int lrow = t >> 2;           // 0..63
    const int lcg  = (t & 3) * 4;      // 0,4,8,12
    const int ty = t >> 4;             // 0..15
    const int tx = t & 15;             // 0..15

    int arow = m0 + lrow;
    if (gidx) arow = gidx[arow];
    const float* Aptr = A + (size_t)arow * Kd + lcg;
    const float* Wptr = W + (size_t)(j0 + lrow) * Kd + lcg;

    float acc[4][4];
    #pragma unroll
    for (int i = 0; i < 4; i++)
        #pragma unroll
        for (int j = 0; j < 4; j++) acc[i][j] = 0.f;

    for (int k0 = 0; k0 < Kd; k0 += 16) {
        float4 av = *(const float4*)(Aptr + k0);
        float4 wv = *(const float4*)(Wptr + k0);
        As[lcg + 0][lrow] = av.x; As[lcg + 1][lrow] = av.y;
        As[lcg + 2][lrow] = av.z; As[lcg + 3][lrow] = av.w;
        Ws[lcg + 0][lrow] = wv.x; Ws[lcg + 1][lrow] = wv.y;
        Ws[lcg + 2][lrow] = wv.z; Ws[lcg + 3][lrow] = wv.w;
        __syncthreads();

        #pragma unroll
        for (int kk = 0; kk < 16; kk++) {
            float4 a4 = *(const float4*)&As[kk][ty * 4];
            float4 b4 = *(const float4*)&Ws[kk][tx * 4];
            float a[4] = {a4.x, a4.y, a4.z, a4.w};
            float b[4] = {b4.x, b4.y, b4.z, b4.w};
            #pragma unroll
            for (int i = 0; i < 4; i++)
                #pragma unroll
                for (int j = 0; j < 4; j++)
                    acc[i][j] += a[i] * b[j];
        }
        __syncthreads();
    }

    float4 bv = *(const float4*)(bias + j0 + tx * 4);
    #pragma unroll
    for (int i = 0; i < 4; i++) {
        int m = m0 + ty * 4 + i;
        int orow = sidx ? sidx[m] : m;
        float4 o;
        o.x = acc[i][0] + bv.x;
        o.y = acc[i][1] + bv.y;
        o.z = acc[i][2] + bv.z;
        o.w = acc[i][3] + bv.w;
        *(float4*)(out + (size_t)orow * Ncols + j0 + tx * 4) = o;
    }
}

// ---------------------------------------------------------------------------
// Attention: one block per (patch, head). 256 threads.
//   S = (q*scale) k^T + rpe_bias ; P = softmax(S) ; O = P v
// rpe_num / pos_b passed at runtime (rpe table is (3*rpe_num, H))
// ---------------------------------------------------------------------------
struct AttnSmem {
    float qs[128][65];
    float ks[128][65];
    float vs[128][65];
    float Ps[128][129];
    float rowsum[128];
    int   cx[128], cy[128], cz[128];
    float rp[3][RPE_MAX];
};

__global__ __launch_bounds__(256) void attn_kernel(
    const float* __restrict__ qkv, const int* __restrict__ gcoord,
    const int* __restrict__ order, const float* __restrict__ rpe,
    float* __restrict__ out, int rpe_num, int pos_b)
{
    extern __shared__ char smem_raw[];
    AttnSmem& sm = *reinterpret_cast<AttnSmem*>(smem_raw);
    const int p = blockIdx.x;
    const int h = blockIdx.y;
    const int t = threadIdx.x;

    // Load q/k/v tiles (row-major, stride 65)
    for (int f = t; f < 2048; f += 256) {
        int i  = f >> 4;
        int dg = (f & 15) * 4;
        const float* base = qkv + (size_t)(p * 128 + i) * C3 + h * 64 + dg;
        float4 qv = *(const float4*)(base);
        float4 kv = *(const float4*)(base + 512);
        float4 vv = *(const float4*)(base + 1024);
        sm.qs[i][dg + 0] = qv.x; sm.qs[i][dg + 1] = qv.y; sm.qs[i][dg + 2] = qv.z; sm.qs[i][dg + 3] = qv.w;
        sm.ks[i][dg + 0] = kv.x; sm.ks[i][dg + 1] = kv.y; sm.ks[i][dg + 2] = kv.z; sm.ks[i][dg + 3] = kv.w;
        sm.vs[i][dg + 0] = vv.x; sm.vs[i][dg + 1] = vv.y; sm.vs[i][dg + 2] = vv.z; sm.vs[i][dg + 3] = vv.w;
    }
    if (t < 128) {
        int gi = order[p * 128 + t];
        sm.cx[t] = gcoord[gi * 3 + 0];
        sm.cy[t] = gcoord[gi * 3 + 1];
        sm.cz[t] = gcoord[gi * 3 + 2];
    }
    if (t < 3 * rpe_num) {
        sm.rp[t / rpe_num][t % rpe_num] = rpe[t * H_NUM + h];
    }
    __syncthreads();

    const int ty = t >> 4;   // 0..15 -> rows ty*8..ty*8+7
    const int tx = t & 15;   // 0..15 -> cols tx*8..tx*8+7

    // ---- S = q k^T ----
    float acc[8][8];
    #pragma unroll
    for (int r = 0; r < 8; r++)
        #pragma unroll
        for (int c = 0; c < 8; c++) acc[r][c] = 0.f;

    #pragma unroll 4
    for (int d = 0; d < 64; d++) {
        float a[8], b[8];
        #pragma unroll
        for (int r = 0; r < 8; r++) a[r] = sm.qs[ty * 8 + r][d];
        #pragma unroll
        for (int c = 0; c < 8; c++) b[c] = sm.ks[tx * 8 + c][d];
        #pragma unroll
        for (int r = 0; r < 8; r++)
            #pragma unroll
            for (int c = 0; c < 8; c++)
                acc[r][c] += a[r] * b[c];
    }

    // ---- scale + RPE bias, store scores ----
    const float scale = 0.125f;  // HD^-0.5
    #pragma unroll
    for (int r = 0; r < 8; r++) {
        int i = ty * 8 + r;
        int xi = sm.cx[i], yi = sm.cy[i], zi = sm.cz[i];
        #pragma unroll
        for (int c = 0; c < 8; c++) {
            int j = tx * 8 + c;
            int dx = min(max(xi - sm.cx[j], -pos_b), pos_b) + pos_b;
            int dy = min(max(yi - sm.cy[j], -pos_b), pos_b) + pos_b;
            int dz = min(max(zi - sm.cz[j], -pos_b), pos_b) + pos_b;
            float bias = sm.rp[0][dx] + sm.rp[1][dy] + sm.rp[2][dz];
            sm.Ps[i][j] = acc[r][c] * scale + bias;
        }
    }
    __syncthreads();

    // ---- softmax (unnormalized exp; rowsum kept for PV epilogue) ----
    if (t < 128) {
        float mx = -1e30f;
        #pragma unroll 4
        for (int m = 0; m < 128; m++) mx = fmaxf(mx, sm.Ps[t][m]);
        float s = 0.f;
        #pragma unroll 4
        for (int m = 0; m < 128; m++) {
            float e = __expf(sm.Ps[t][m] - mx);
            s += e;
            sm.Ps[t][m] = e;
        }
        sm.rowsum[t] = s;
    }
    __syncthreads();

    // ---- O = P v : thread rows ty*8..+7, cols tx*4..+3 ----
    float o[8][4];
    #pragma unroll
    for (int r = 0; r < 8; r++)
        #pragma unroll
        for (int c = 0; c < 4; c++) o[r][c] = 0.f;

    #pragma unroll 4
    for (int m = 0; m < 128; m++) {
        float a[8], b[4];
        #pragma unroll
        for (int r = 0; r < 8; r++) a[r] = sm.Ps[ty * 8 + r][m];
        #pragma unroll
        for (int c = 0; c < 4; c++) b[c] = sm.vs[m][tx * 4 + c];
        #pragma unroll
        for (int r = 0; r < 8; r++)
            #pragma unroll
            for (int c = 0; c < 4; c++)
                o[r][c] += a[r] * b[c];
    }

    #pragma unroll
    for (int r = 0; r < 8; r++) {
        int i = ty * 8 + r;
        float inv = 1.f / sm.rowsum[i];
        float4 ov;
        ov.x = o[r][0] * inv;
        ov.y = o[r][1] * inv;
        ov.z = o[r][2] * inv;
        ov.w = o[r][3] * inv;
        *(float4*)(out + (size_t)(p * 128 + i) * C_DIM + h * 64 + tx * 4) = ov;
    }
}

// ---------------------------------------------------------------------------
extern "C" void kernel_launch(void* const* d_in, const int* in_sizes, int n_in,
                              void* d_out, int out_size)
{
    const float* feat   = (const float*)d_in[0];
    const int*   gcoord = (const int*)  d_in[1];
    const int*   order  = (const int*)  d_in[2];
    // d_in[3] = inverse (unused: scatter via order)
    const float* qkv_w  = (const float*)d_in[4];
    const float* qkv_b  = (const float*)d_in[5];
    const float* proj_w = (const float*)d_in[6];
    const float* proj_b = (const float*)d_in[7];
    const float* rpe    = (const float*)d_in[8];
    float* out = (float*)d_out;

    // rpe_table is (3*rpe_num, H): derive actual rpe_num from element count.
    // (Reference comment claims 33 but int((4K)^(1/3)*2) = 15 -> rpe_num = 31.)
    int rpe_num = in_sizes[8] / (3 * H_NUM);
    if (rpe_num > RPE_MAX) rpe_num = RPE_MAX;
    int pos_b = (rpe_num - 1) / 2;

    float *qkv_buf = nullptr, *ao_buf = nullptr;
    cudaGetSymbolAddress((void**)&qkv_buf, g_qkv);
    cudaGetSymbolAddress((void**)&ao_buf,  g_ao);

    cudaFuncSetAttribute(attn_kernel,
                         cudaFuncAttributeMaxDynamicSharedMemorySize,
                         (int)sizeof(AttnSmem));

    // Stage 1: gather + QKV projection
    dim3 g1(C3 / 64, N_TOT / 64);
    gemm_nt<<<g1, 256>>>(feat, qkv_w, qkv_b, qkv_buf, order, nullptr, C3, C_DIM);

    // Stage 2: per-(patch, head) attention with RPE
    dim3 ga(P_NUM, H_NUM);
    attn_kernel<<<ga, 256, sizeof(AttnSmem)>>>(qkv_buf, gcoord, order, rpe,
                                               ao_buf, rpe_num, pos_b);

    // Stage 3: output projection + scatter back to input order
    dim3 g3(C_DIM / 64, N_TOT / 64);
    gemm_nt<<<g3, 256>>>(ao_buf, proj_w, proj_b, out, nullptr, order, C_DIM, C_DIM);
}

// round 3
// speedup vs baseline: 2.0355x; 2.0355x over previous
#include <cuda_runtime.h>
#include <math.h>
#include <stdint.h>

#define N_TOT   131072
#define C_DIM   512
#define H_NUM   8
#define K_PATCH 128
#define HD_DIM  64
#define P_NUM   1024          // N_TOT / K_PATCH
#define C3      1536          // 3 * C_DIM
#define RPE_MAX 33            // smem capacity; actual rpe_num passed at runtime

// Scratch (device globals: allowed; no cudaMalloc anywhere)
static __device__ float g_qkv[(size_t)N_TOT * C3];    // 805 MB
static __device__ float g_ao [(size_t)N_TOT * C_DIM]; // 268 MB

__device__ __forceinline__ uint32_t f2tf32(float x) {
    uint32_t r;
    asm("cvt.rna.tf32.f32 %0, %1;" : "=r"(r) : "f"(x));
    return r;
}

__device__ __forceinline__ void mma_tf32(float* d,
                                         uint32_t a0, uint32_t a1, uint32_t a2, uint32_t a3,
                                         uint32_t b0, uint32_t b1)
{
    asm volatile(
        "mma.sync.aligned.m16n8k8.row.col.f32.tf32.tf32.f32 "
        "{%0,%1,%2,%3}, {%4,%5,%6,%7}, {%8,%9}, {%0,%1,%2,%3};"
        : "+f"(d[0]), "+f"(d[1]), "+f"(d[2]), "+f"(d[3])
        : "r"(a0), "r"(a1), "r"(a2), "r"(a3), "r"(b0), "r"(b1));
}

// ---------------------------------------------------------------------------
// TF32 tensor-core GEMM (NT): out[row(m), j] = sum_c A[arow(m), c]*W[j, c] + b[j]
//   arow(m) = gidx ? gidx[m] : m   (gather)   row(m) = sidx ? sidx[m] : m (scatter)
// BM=BN=128, BK=16, 256 threads (8 warps, each 32m x 64n), double-buffered.
// ---------------------------------------------------------------------------
#define LDA 17   // smem row stride (16 cols + 1 pad)

__global__ __launch_bounds__(256) void gemm_tf32(
    const float* __restrict__ A, const float* __restrict__ W,
    const float* __restrict__ bias, float* __restrict__ out,
    const int* __restrict__ gidx, const int* __restrict__ sidx,
    int Ncols, int Kd)
{
    __shared__ __align__(16) uint32_t As[2][128 * LDA];
    __shared__ __align__(16) uint32_t Ws[2][128 * LDA];

    const int m0 = blockIdx.y * 128;
    const int j0 = blockIdx.x * 128;
    const int t  = threadIdx.x;
    const int warp = t >> 5;
    const int lane = t & 31;
    const int wm = warp & 3;        // 4 warps over M (32 rows each)
    const int wn = warp >> 2;       // 2 warps over N (64 cols each)
    const int gr = lane >> 2;       // 0..7
    const int gc = lane & 3;        // 0..3

    // Global-load mapping: thread loads 8 consecutive floats of one row.
    const int lrow = t >> 1;          // 0..127
    const int lcb  = (t & 1) * 8;     // 0 or 8

    int arow = m0 + lrow;
    if (gidx) arow = gidx[arow];
    const float* Ag = A + (size_t)arow * Kd + lcb;
    const float* Wg = W + (size_t)(j0 + lrow) * Kd + lcb;

    float acc[2][8][4];
    #pragma unroll
    for (int mt = 0; mt < 2; mt++)
        #pragma unroll
        for (int nt = 0; nt < 8; nt++)
            #pragma unroll
            for (int i = 0; i < 4; i++) acc[mt][nt][i] = 0.f;

    const int iters = Kd >> 4;

    // Preload tile 0
    {
        float4 a0 = *(const float4*)(Ag);
        float4 a1 = *(const float4*)(Ag + 4);
        float4 w0 = *(const float4*)(Wg);
        float4 w1 = *(const float4*)(Wg + 4);
        uint32_t* ap = &As[0][lrow * LDA + lcb];
        uint32_t* wp = &Ws[0][lrow * LDA + lcb];
        ap[0]=f2tf32(a0.x); ap[1]=f2tf32(a0.y); ap[2]=f2tf32(a0.z); ap[3]=f2tf32(a0.w);
        ap[4]=f2tf32(a1.x); ap[5]=f2tf32(a1.y); ap[6]=f2tf32(a1.z); ap[7]=f2tf32(a1.w);
        wp[0]=f2tf32(w0.x); wp[1]=f2tf32(w0.y); wp[2]=f2tf32(w0.z); wp[3]=f2tf32(w0.w);
        wp[4]=f2tf32(w1.x); wp[5]=f2tf32(w1.y); wp[6]=f2tf32(w1.z); wp[7]=f2tf32(w1.w);
    }
    __syncthreads();

    for (int it = 0; it < iters; it++) {
        const int buf = it & 1;
        float4 a0, a1, w0, w1;
        const bool have_next = (it + 1 < iters);
        if (have_next) {
            const float* Agn = Ag + (size_t)(it + 1) * 16;
            const float* Wgn = Wg + (size_t)(it + 1) * 16;
            a0 = *(const float4*)(Agn);
            a1 = *(const float4*)(Agn + 4);
            w0 = *(const float4*)(Wgn);
            w1 = *(const float4*)(Wgn + 4);
        }

        const uint32_t* Ab = As[buf];
        const uint32_t* Wb = Ws[buf];
        #pragma unroll
        for (int ks = 0; ks < 2; ks++) {
            const int kb = ks * 8;
            uint32_t bf[8][2];
            #pragma unroll
            for (int nt = 0; nt < 8; nt++) {
                int n = wn * 64 + nt * 8 + gr;
                bf[nt][0] = Wb[n * LDA + kb + gc];
                bf[nt][1] = Wb[n * LDA + kb + gc + 4];
            }
            #pragma unroll
            for (int mt = 0; mt < 2; mt++) {
                int r0 = wm * 32 + mt * 16 + gr;
                uint32_t fa0 = Ab[r0 * LDA + kb + gc];
                uint32_t fa1 = Ab[(r0 + 8) * LDA + kb + gc];
                uint32_t fa2 = Ab[r0 * LDA + kb + gc + 4];
                uint32_t fa3 = Ab[(r0 + 8) * LDA + kb + gc + 4];
                #pragma unroll
                for (int nt = 0; nt < 8; nt++)
                    mma_tf32(acc[mt][nt], fa0, fa1, fa2, fa3, bf[nt][0], bf[nt][1]);
            }
        }

        if (have_next) {
            uint32_t* ap = &As[buf ^ 1][lrow * LDA + lcb];
            uint32_t* wp = &Ws[buf ^ 1][lrow * LDA + lcb];
            ap[0]=f2tf32(a0.x); ap[1]=f2tf32(a0.y); ap[2]=f2tf32(a0.z); ap[3]=f2tf32(a0.w);
            ap[4]=f2tf32(a1.x); ap[5]=f2tf32(a1.y); ap[6]=f2tf32(a1.z); ap[7]=f2tf32(a1.w);
            wp[0]=f2tf32(w0.x); wp[1]=f2tf32(w0.y); wp[2]=f2tf32(w0.z); wp[3]=f2tf32(w0.w);
            wp[4]=f2tf32(w1.x); wp[5]=f2tf32(w1.y); wp[6]=f2tf32(w1.z); wp[7]=f2tf32(w1.w);
        }
        __syncthreads();
    }

    // Epilogue: bias + (optional scatter) store, float2 per accumulator pair
    #pragma unroll
    for (int mt = 0; mt < 2; mt++) {
        int m_a = m0 + wm * 32 + mt * 16 + gr;       // rows gr and gr+8
        int m_b = m_a + 8;
        int orow_a = sidx ? sidx[m_a] : m_a;
        int orow_b = sidx ? sidx[m_b] : m_b;
        #pragma unroll
        for (int nt = 0; nt < 8; nt++) {
            int col = j0 + wn * 64 + nt * 8 + gc * 2;
            float b0 = bias[col], b1 = bias[col + 1];
            float2 v0 = make_float2(acc[mt][nt][0] + b0, acc[mt][nt][1] + b1);
            float2 v1 = make_float2(acc[mt][nt][2] + b0, acc[mt][nt][3] + b1);
            *(float2*)(out + (size_t)orow_a * Ncols + col) = v0;
            *(float2*)(out + (size_t)orow_b * Ncols + col) = v1;
        }
    }
}

// ---------------------------------------------------------------------------
// Attention: one block per (patch, head). 256 threads.
//   S = (q*scale) k^T + rpe_bias ; P = softmax(S) ; O = P v
// ---------------------------------------------------------------------------
struct AttnSmem {
    float qs[128][65];
    float ks[128][65];
    float vs[128][65];
    float Ps[128][129];
    float rowsum[128];
    int   cx[128], cy[128], cz[128];
    float rp[3][RPE_MAX];
};

__global__ __launch_bounds__(256) void attn_kernel(
    const float* __restrict__ qkv, const int* __restrict__ gcoord,
    const int* __restrict__ order, const float* __restrict__ rpe,
    float* __restrict__ out, int rpe_num, int pos_b)
{
    extern __shared__ char smem_raw[];
    AttnSmem& sm = *reinterpret_cast<AttnSmem*>(smem_raw);
    const int p = blockIdx.x;
    const int h = blockIdx.y;
    const int t = threadIdx.x;

    for (int f = t; f < 2048; f += 256) {
        int i  = f >> 4;
        int dg = (f & 15) * 4;
        const float* base = qkv + (size_t)(p * 128 + i) * C3 + h * 64 + dg;
        float4 qv = *(const float4*)(base);
        float4 kv = *(const float4*)(base + 512);
        float4 vv = *(const float4*)(base + 1024);
        sm.qs[i][dg + 0] = qv.x; sm.qs[i][dg + 1] = qv.y; sm.qs[i][dg + 2] = qv.z; sm.qs[i][dg + 3] = qv.w;
        sm.ks[i][dg + 0] = kv.x; sm.ks[i][dg + 1] = kv.y; sm.ks[i][dg + 2] = kv.z; sm.ks[i][dg + 3] = kv.w;
        sm.vs[i][dg + 0] = vv.x; sm.vs[i][dg + 1] = vv.y; sm.vs[i][dg + 2] = vv.z; sm.vs[i][dg + 3] = vv.w;
    }
    if (t < 128) {
        int gi = order[p * 128 + t];
        sm.cx[t] = gcoord[gi * 3 + 0];
        sm.cy[t] = gcoord[gi * 3 + 1];
        sm.cz[t] = gcoord[gi * 3 + 2];
    }
    if (t < 3 * rpe_num) {
        sm.rp[t / rpe_num][t % rpe_num] = rpe[t * H_NUM + h];
    }
    __syncthreads();

    const int ty = t >> 4;
    const int tx = t & 15;

    float acc[8][8];
    #pragma unroll
    for (int r = 0; r < 8; r++)
        #pragma unroll
        for (int c = 0; c < 8; c++) acc[r][c] = 0.f;

    #pragma unroll 4
    for (int d = 0; d < 64; d++) {
        float a[8], b[8];
        #pragma unroll
        for (int r = 0; r < 8; r++) a[r] = sm.qs[ty * 8 + r][d];
        #pragma unroll
        for (int c = 0; c < 8; c++) b[c] = sm.ks[tx * 8 + c][d];
        #pragma unroll
        for (int r = 0; r < 8; r++)
            #pragma unroll
            for (int c = 0; c < 8; c++)
                acc[r][c] += a[r] * b[c];
    }

    const float scale = 0.125f;
    #pragma unroll
    for (int r = 0; r < 8; r++) {
        int i = ty * 8 + r;
        int xi = sm.cx[i], yi = sm.cy[i], zi = sm.cz[i];
        #pragma unroll
        for (int c = 0; c < 8; c++) {
            int j = tx * 8 + c;
            int dx = min(max(xi - sm.cx[j], -pos_b), pos_b) + pos_b;
            int dy = min(max(yi - sm.cy[j], -pos_b), pos_b) + pos_b;
            int dz = min(max(zi - sm.cz[j], -pos_b), pos_b) + pos_b;
            float bias = sm.rp[0][dx] + sm.rp[1][dy] + sm.rp[2][dz];
            sm.Ps[i][j] = acc[r][c] * scale + bias;
        }
    }
    __syncthreads();

    if (t < 128) {
        float mx = -1e30f;
        #pragma unroll 4
        for (int m = 0; m < 128; m++) mx = fmaxf(mx, sm.Ps[t][m]);
        float s = 0.f;
        #pragma unroll 4
        for (int m = 0; m < 128; m++) {
            float e = __expf(sm.Ps[t][m] - mx);
            s += e;
            sm.Ps[t][m] = e;
        }
        sm.rowsum[t] = s;
    }
    __syncthreads();

    float o[8][4];
    #pragma unroll
    for (int r = 0; r < 8; r++)
        #pragma unroll
        for (int c = 0; c < 4; c++) o[r][c] = 0.f;

    #pragma unroll 4
    for (int m = 0; m < 128; m++) {
        float a[8], b[4];
        #pragma unroll
        for (int r = 0; r < 8; r++) a[r] = sm.Ps[ty * 8 + r][m];
        #pragma unroll
        for (int c = 0; c < 4; c++) b[c] = sm.vs[m][tx * 4 + c];
        #pragma unroll
        for (int r = 0; r < 8; r++)
            #pragma unroll
            for (int c = 0; c < 4; c++)
                o[r][c] += a[r] * b[c];
    }

    #pragma unroll
    for (int r = 0; r < 8; r++) {
        int i = ty * 8 + r;
        float inv = 1.f / sm.rowsum[i];
        float4 ov;
        ov.x = o[r][0] * inv;
        ov.y = o[r][1] * inv;
        ov.z = o[r][2] * inv;
        ov.w = o[r][3] * inv;
        *(float4*)(out + (size_t)(p * 128 + i) * C_DIM + h * 64 + tx * 4) = ov;
    }
}

// ---------------------------------------------------------------------------
extern "C" void kernel_launch(void* const* d_in, const int* in_sizes, int n_in,
                              void* d_out, int out_size)
{
    const float* feat   = (const float*)d_in[0];
    const int*   gcoord = (const int*)  d_in[1];
    const int*   order  = (const int*)  d_in[2];
    // d_in[3] = inverse (unused: scatter via order)
    const float* qkv_w  = (const float*)d_in[4];
    const float* qkv_b  = (const float*)d_in[5];
    const float* proj_w = (const float*)d_in[6];
    const float* proj_b = (const float*)d_in[7];
    const float* rpe    = (const float*)d_in[8];
    float* out = (float*)d_out;

    // rpe_table is (3*rpe_num, H): derive rpe_num from element count (31, not 33!)
    int rpe_num = in_sizes[8] / (3 * H_NUM);
    if (rpe_num > RPE_MAX) rpe_num = RPE_MAX;
    int pos_b = (rpe_num - 1) / 2;

    float *qkv_buf = nullptr, *ao_buf = nullptr;
    cudaGetSymbolAddress((void**)&qkv_buf, g_qkv);
    cudaGetSymbolAddress((void**)&ao_buf,  g_ao);

    cudaFuncSetAttribute(attn_kernel,
                         cudaFuncAttributeMaxDynamicSharedMemorySize,
                         (int)sizeof(AttnSmem));

    // Stage 1: gather + QKV projection (tf32 tensor cores)
    dim3 g1(C3 / 128, N_TOT / 128);
    gemm_tf32<<<g1, 256>>>(feat, qkv_w, qkv_b, qkv_buf, order, nullptr, C3, C_DIM);

    // Stage 2: per-(patch, head) attention with RPE
    dim3 ga(P_NUM, H_NUM);
    attn_kernel<<<ga, 256, sizeof(AttnSmem)>>>(qkv_buf, gcoord, order, rpe,
                                               ao_buf, rpe_num, pos_b);

    // Stage 3: output projection + scatter (tf32 tensor cores)
    dim3 g3(C_DIM / 128, N_TOT / 128);
    gemm_tf32<<<g3, 256>>>(ao_buf, proj_w, proj_b, out, nullptr, order, C_DIM, C_DIM);
}

// round 4
// speedup vs baseline: 2.9720x; 1.4601x over previous
#include <cuda_runtime.h>
#include <math.h>
#include <stdint.h>

#define N_TOT   131072
#define C_DIM   512
#define H_NUM   8
#define K_PATCH 128
#define HD_DIM  64
#define P_NUM   1024
#define C3      1536
#define RPE_MAX 33

static __device__ float g_qkv[(size_t)N_TOT * C3];
static __device__ float g_ao [(size_t)N_TOT * C_DIM];

__device__ __forceinline__ uint32_t f2tf32(float x) {
    uint32_t r;
    asm("cvt.rna.tf32.f32 %0, %1;" : "=r"(r) : "f"(x));
    return r;
}
__device__ __forceinline__ uint32_t sptr(const void* p) {
    return (uint32_t)__cvta_generic_to_shared(p);
}
__device__ __forceinline__ void ldsm_x4(uint32_t& r0, uint32_t& r1,
                                        uint32_t& r2, uint32_t& r3, uint32_t addr) {
    asm volatile("ldmatrix.sync.aligned.m8n8.x4.shared.b16 {%0,%1,%2,%3}, [%4];"
                 : "=r"(r0), "=r"(r1), "=r"(r2), "=r"(r3) : "r"(addr));
}
__device__ __forceinline__ void mma_tf32(float* d,
                                         uint32_t a0, uint32_t a1, uint32_t a2, uint32_t a3,
                                         uint32_t b0, uint32_t b1)
{
    asm volatile(
        "mma.sync.aligned.m16n8k8.row.col.f32.tf32.tf32.f32 "
        "{%0,%1,%2,%3}, {%4,%5,%6,%7}, {%8,%9}, {%0,%1,%2,%3};"
        : "+f"(d[0]), "+f"(d[1]), "+f"(d[2]), "+f"(d[3])
        : "r"(a0), "r"(a1), "r"(a2), "r"(a3), "r"(b0), "r"(b1));
}

// ---------------------------------------------------------------------------
// TF32 tensor-core GEMM (NT), ldmatrix fragment loads.
// BM=BN=128, BK=16, 256 threads (8 warps, 32m x 64n each), double-buffered.
// ---------------------------------------------------------------------------
#define LDA 20   // 16 k-words + 4 pad: 20r mod 32 partitions banks perfectly

__global__ __launch_bounds__(256) void gemm_tf32(
    const float* __restrict__ A, const float* __restrict__ W,
    const float* __restrict__ bias, float* __restrict__ out,
    const int* __restrict__ gidx, const int* __restrict__ sidx,
    int Ncols, int Kd)
{
    __shared__ __align__(16) uint32_t As[2][128 * LDA];
    __shared__ __align__(16) uint32_t Ws[2][128 * LDA];

    const int m0 = blockIdx.y * 128;
    const int j0 = blockIdx.x * 128;
    const int t  = threadIdx.x;
    const int lane = t & 31;
    const int warp = t >> 5;
    const int wm = warp & 3;
    const int wn = warp >> 2;

    const int lrow = t >> 1;
    const int lcb  = (t & 1) * 8;

    int arow = m0 + lrow;
    if (gidx) arow = gidx[arow];
    const float* Ag = A + (size_t)arow * Kd + lcb;
    const float* Wg = W + (size_t)(j0 + lrow) * Kd + lcb;

    float acc[2][8][4];
    #pragma unroll
    for (int mt = 0; mt < 2; mt++)
        #pragma unroll
        for (int nt = 0; nt < 8; nt++)
            #pragma unroll
            for (int i = 0; i < 4; i++) acc[mt][nt][i] = 0.f;

    const int iters = Kd >> 4;

    {
        float4 a0 = *(const float4*)(Ag);
        float4 a1 = *(const float4*)(Ag + 4);
        float4 w0 = *(const float4*)(Wg);
        float4 w1 = *(const float4*)(Wg + 4);
        uint32_t* ap = &As[0][lrow * LDA + lcb];
        uint32_t* wp = &Ws[0][lrow * LDA + lcb];
        ap[0]=f2tf32(a0.x); ap[1]=f2tf32(a0.y); ap[2]=f2tf32(a0.z); ap[3]=f2tf32(a0.w);
        ap[4]=f2tf32(a1.x); ap[5]=f2tf32(a1.y); ap[6]=f2tf32(a1.z); ap[7]=f2tf32(a1.w);
        wp[0]=f2tf32(w0.x); wp[1]=f2tf32(w0.y); wp[2]=f2tf32(w0.z); wp[3]=f2tf32(w0.w);
        wp[4]=f2tf32(w1.x); wp[5]=f2tf32(w1.y); wp[6]=f2tf32(w1.z); wp[7]=f2tf32(w1.w);
    }
    __syncthreads();

    // ldmatrix lane-address components
    const int a_roff = (lane & 7) + ((lane & 8) ? 8 : 0);   // A: rows, quads 0/1
    const int a_coff = (lane & 16) ? 4 : 0;                 // A: k, quads 2/3
    const int b_roff = (lane & 7) + ((lane & 16) ? 8 : 0);  // B: rows, quads 2/3 = next nt
    const int b_coff = (lane & 8) ? 4 : 0;                  // B: k, quads 1/3

    for (int it = 0; it < iters; it++) {
        const int buf = it & 1;
        float4 a0, a1, w0, w1;
        const bool have_next = (it + 1 < iters);
        if (have_next) {
            const float* Agn = Ag + (size_t)(it + 1) * 16;
            const float* Wgn = Wg + (size_t)(it + 1) * 16;
            a0 = *(const float4*)(Agn);
            a1 = *(const float4*)(Agn + 4);
            w0 = *(const float4*)(Wgn);
            w1 = *(const float4*)(Wgn + 4);
        }

        const uint32_t* Ab = As[buf];
        const uint32_t* Wb = Ws[buf];
        #pragma unroll
        for (int ks = 0; ks < 2; ks++) {
            const int kb = ks * 8;
            uint32_t bf[8][2];
            #pragma unroll
            for (int ntp = 0; ntp < 4; ntp++) {
                uint32_t addr = sptr(&Wb[(wn * 64 + ntp * 16 + b_roff) * LDA + kb + b_coff]);
                ldsm_x4(bf[2*ntp][0], bf[2*ntp][1], bf[2*ntp+1][0], bf[2*ntp+1][1], addr);
            }
            #pragma unroll
            for (int mt = 0; mt < 2; mt++) {
                uint32_t fa0, fa1, fa2, fa3;
                uint32_t addr = sptr(&Ab[(wm * 32 + mt * 16 + a_roff) * LDA + kb + a_coff]);
                ldsm_x4(fa0, fa1, fa2, fa3, addr);
                #pragma unroll
                for (int nt = 0; nt < 8; nt++)
                    mma_tf32(acc[mt][nt], fa0, fa1, fa2, fa3, bf[nt][0], bf[nt][1]);
            }
        }

        if (have_next) {
            uint32_t* ap = &As[buf ^ 1][lrow * LDA + lcb];
            uint32_t* wp = &Ws[buf ^ 1][lrow * LDA + lcb];
            ap[0]=f2tf32(a0.x); ap[1]=f2tf32(a0.y); ap[2]=f2tf32(a0.z); ap[3]=f2tf32(a0.w);
            ap[4]=f2tf32(a1.x); ap[5]=f2tf32(a1.y); ap[6]=f2tf32(a1.z); ap[7]=f2tf32(a1.w);
            wp[0]=f2tf32(w0.x); wp[1]=f2tf32(w0.y); wp[2]=f2tf32(w0.z); wp[3]=f2tf32(w0.w);
            wp[4]=f2tf32(w1.x); wp[5]=f2tf32(w1.y); wp[6]=f2tf32(w1.z); wp[7]=f2tf32(w1.w);
        }
        __syncthreads();
    }

    const int gr = lane >> 2;
    const int gc = lane & 3;
    #pragma unroll
    for (int mt = 0; mt < 2; mt++) {
        int m_a = m0 + wm * 32 + mt * 16 + gr;
        int m_b = m_a + 8;
        int orow_a = sidx ? sidx[m_a] : m_a;
        int orow_b = sidx ? sidx[m_b] : m_b;
        #pragma unroll
        for (int nt = 0; nt < 8; nt++) {
            int col = j0 + wn * 64 + nt * 8 + gc * 2;
            float b0 = bias[col], b1 = bias[col + 1];
            float2 v0 = make_float2(acc[mt][nt][0] + b0, acc[mt][nt][1] + b1);
            float2 v1 = make_float2(acc[mt][nt][2] + b0, acc[mt][nt][3] + b1);
            *(float2*)(out + (size_t)orow_a * Ncols + col) = v0;
            *(float2*)(out + (size_t)orow_b * Ncols + col) = v1;
        }
    }
}

// ---------------------------------------------------------------------------
// Attention (tf32 MMA): one block per (patch, head), 8 warps.
// Warp w owns score rows 16w..16w+15 through QK^T, softmax, PV.
// ---------------------------------------------------------------------------
#define LQ 68    // 64 + 4 pad (tf32 words)
#define LP 132   // 128 + 4 pad

struct __align__(16) AttnSmem {
    uint32_t qs[128 * LQ];   // q tf32, row i, col d
    uint32_t ks[128 * LQ];   // k tf32, row j, col d
    uint32_t vt[64 * LP];    // v^T tf32, row d, col m
    float    Ps[128 * LP];   // scores fp32 -> exp tf32 bits in place
    float    rowsum[128];
    int      cx[128], cy[128], cz[128];
    float    rp[3][RPE_MAX];
};

__global__ __launch_bounds__(256) void attn_kernel(
    const float* __restrict__ qkv, const int* __restrict__ gcoord,
    const int* __restrict__ order, const float* __restrict__ rpe,
    float* __restrict__ out, int rpe_num, int pos_b)
{
    extern __shared__ char smem_raw[];
    AttnSmem& sm = *reinterpret_cast<AttnSmem*>(smem_raw);
    const int p = blockIdx.x;
    const int h = blockIdx.y;
    const int t = threadIdx.x;
    const int lane = t & 31;
    const int warp = t >> 5;

    // ---- load q/k (tf32), v transposed (tf32) ----
    for (int f = t; f < 2048; f += 256) {
        int i  = f >> 4;
        int dg = (f & 15) * 4;
        const float* base = qkv + (size_t)(p * 128 + i) * C3 + h * 64 + dg;
        float4 qv = *(const float4*)(base);
        float4 kv = *(const float4*)(base + 512);
        float4 vv = *(const float4*)(base + 1024);
        uint32_t* qp = &sm.qs[i * LQ + dg];
        uint32_t* kp = &sm.ks[i * LQ + dg];
        qp[0]=f2tf32(qv.x); qp[1]=f2tf32(qv.y); qp[2]=f2tf32(qv.z); qp[3]=f2tf32(qv.w);
        kp[0]=f2tf32(kv.x); kp[1]=f2tf32(kv.y); kp[2]=f2tf32(kv.z); kp[3]=f2tf32(kv.w);
        sm.vt[(dg + 0) * LP + i] = f2tf32(vv.x);
        sm.vt[(dg + 1) * LP + i] = f2tf32(vv.y);
        sm.vt[(dg + 2) * LP + i] = f2tf32(vv.z);
        sm.vt[(dg + 3) * LP + i] = f2tf32(vv.w);
    }
    if (t < 128) {
        int gi = order[p * 128 + t];
        sm.cx[t] = gcoord[gi * 3 + 0];
        sm.cy[t] = gcoord[gi * 3 + 1];
        sm.cz[t] = gcoord[gi * 3 + 2];
    }
    if (t < 3 * rpe_num) {
        sm.rp[t / rpe_num][t % rpe_num] = rpe[t * H_NUM + h];
    }
    __syncthreads();

    const int m0w = warp * 16;
    const int a_roff = (lane & 7) + ((lane & 8) ? 8 : 0);
    const int a_coff = (lane & 16) ? 4 : 0;
    const int b_roff = (lane & 7) + ((lane & 16) ? 8 : 0);
    const int b_coff = (lane & 8) ? 4 : 0;
    const int gr = lane >> 2;
    const int gc = lane & 3;

    // ---- QK^T : acc[nt][4], nt over 16 n-tiles of 8 ----
    float acc[16][4];
    #pragma unroll
    for (int nt = 0; nt < 16; nt++)
        #pragma unroll
        for (int i = 0; i < 4; i++) acc[nt][i] = 0.f;

    #pragma unroll
    for (int d0 = 0; d0 < 64; d0 += 8) {
        uint32_t a0, a1, a2, a3;
        ldsm_x4(a0, a1, a2, a3,
                sptr(&sm.qs[(m0w + a_roff) * LQ + d0 + a_coff]));
        #pragma unroll
        for (int ntp = 0; ntp < 8; ntp++) {
            uint32_t b0, b1, c0, c1;
            ldsm_x4(b0, b1, c0, c1,
                    sptr(&sm.ks[(ntp * 16 + b_roff) * LQ + d0 + b_coff]));
            mma_tf32(acc[2*ntp],     a0, a1, a2, a3, b0, b1);
            mma_tf32(acc[2*ntp + 1], a0, a1, a2, a3, c0, c1);
        }
    }

    // ---- scale + RPE bias -> Ps (fp32) ----
    const float scale = 0.125f;
    const int i0 = m0w + gr, i1 = i0 + 8;
    const int x0 = sm.cx[i0], y0 = sm.cy[i0], z0 = sm.cz[i0];
    const int x1 = sm.cx[i1], y1 = sm.cy[i1], z1 = sm.cz[i1];
    #pragma unroll
    for (int nt = 0; nt < 16; nt++) {
        int j0c = nt * 8 + gc * 2;
        #pragma unroll
        for (int jj = 0; jj < 2; jj++) {
            int j = j0c + jj;
            int xj = sm.cx[j], yj = sm.cy[j], zj = sm.cz[j];
            int dx0 = min(max(x0 - xj, -pos_b), pos_b) + pos_b;
            int dy0 = min(max(y0 - yj, -pos_b), pos_b) + pos_b;
            int dz0 = min(max(z0 - zj, -pos_b), pos_b) + pos_b;
            int dx1 = min(max(x1 - xj, -pos_b), pos_b) + pos_b;
            int dy1 = min(max(y1 - yj, -pos_b), pos_b) + pos_b;
            int dz1 = min(max(z1 - zj, -pos_b), pos_b) + pos_b;
            float bias0 = sm.rp[0][dx0] + sm.rp[1][dy0] + sm.rp[2][dz0];
            float bias1 = sm.rp[0][dx1] + sm.rp[1][dy1] + sm.rp[2][dz1];
            sm.Ps[i0 * LP + j] = acc[nt][jj]     * scale + bias0;
            sm.Ps[i1 * LP + j] = acc[nt][jj + 2] * scale + bias1;
        }
    }
    __syncwarp();

    // ---- softmax over warp-owned rows; write exp back as tf32 bits ----
    #pragma unroll 2
    for (int r = 0; r < 16; r++) {
        int row = m0w + r;
        float v0 = sm.Ps[row * LP + lane];
        float v1 = sm.Ps[row * LP + lane + 32];
        float v2 = sm.Ps[row * LP + lane + 64];
        float v3 = sm.Ps[row * LP + lane + 96];
        float mx = fmaxf(fmaxf(v0, v1), fmaxf(v2, v3));
        #pragma unroll
        for (int s = 16; s > 0; s >>= 1)
            mx = fmaxf(mx, __shfl_xor_sync(0xffffffffu, mx, s));
        float e0 = __expf(v0 - mx), e1 = __expf(v1 - mx);
        float e2 = __expf(v2 - mx), e3 = __expf(v3 - mx);
        float s4 = (e0 + e1) + (e2 + e3);
        #pragma unroll
        for (int s = 16; s > 0; s >>= 1)
            s4 += __shfl_xor_sync(0xffffffffu, s4, s);
        sm.Ps[row * LP + lane]      = __uint_as_float(f2tf32(e0));
        sm.Ps[row * LP + lane + 32] = __uint_as_float(f2tf32(e1));
        sm.Ps[row * LP + lane + 64] = __uint_as_float(f2tf32(e2));
        sm.Ps[row * LP + lane + 96] = __uint_as_float(f2tf32(e3));
        if (lane == 0) sm.rowsum[row] = s4;
    }
    __syncwarp();

    // ---- PV : o[nt][4], nt over 8 n-tiles (64 cols) ----
    float o[8][4];
    #pragma unroll
    for (int nt = 0; nt < 8; nt++)
        #pragma unroll
        for (int i = 0; i < 4; i++) o[nt][i] = 0.f;

    const uint32_t* Pu = (const uint32_t*)sm.Ps;
    #pragma unroll
    for (int m0 = 0; m0 < 128; m0 += 8) {
        uint32_t a0, a1, a2, a3;
        ldsm_x4(a0, a1, a2, a3,
                sptr(&Pu[(m0w + a_roff) * LP + m0 + a_coff]));
        #pragma unroll
        for (int ntp = 0; ntp < 4; ntp++) {
            uint32_t b0, b1, c0, c1;
            ldsm_x4(b0, b1, c0, c1,
                    sptr(&sm.vt[(ntp * 16 + b_roff) * LP + m0 + b_coff]));
            mma_tf32(o[2*ntp],     a0, a1, a2, a3, b0, b1);
            mma_tf32(o[2*ntp + 1], a0, a1, a2, a3, c0, c1);
        }
    }

    // ---- normalize + store ----
    const float inv0 = 1.f / sm.rowsum[i0];
    const float inv1 = 1.f / sm.rowsum[i1];
    #pragma unroll
    for (int nt = 0; nt < 8; nt++) {
        int col = h * 64 + nt * 8 + gc * 2;
        float2 w0 = make_float2(o[nt][0] * inv0, o[nt][1] * inv0);
        float2 w1 = make_float2(o[nt][2] * inv1, o[nt][3] * inv1);
        *(float2*)(out + (size_t)(p * 128 + i0) * C_DIM + col) = w0;
        *(float2*)(out + (size_t)(p * 128 + i1) * C_DIM + col) = w1;
    }
}

// ---------------------------------------------------------------------------
extern "C" void kernel_launch(void* const* d_in, const int* in_sizes, int n_in,
                              void* d_out, int out_size)
{
    const float* feat   = (const float*)d_in[0];
    const int*   gcoord = (const int*)  d_in[1];
    const int*   order  = (const int*)  d_in[2];
    const float* qkv_w  = (const float*)d_in[4];
    const float* qkv_b  = (const float*)d_in[5];
    const float* proj_w = (const float*)d_in[6];
    const float* proj_b = (const float*)d_in[7];
    const float* rpe    = (const float*)d_in[8];
    float* out = (float*)d_out;

    int rpe_num = in_sizes[8] / (3 * H_NUM);   // 31 (NOT 33 — ref comment is wrong)
    if (rpe_num > RPE_MAX) rpe_num = RPE_MAX;
    int pos_b = (rpe_num - 1) / 2;

    float *qkv_buf = nullptr, *ao_buf = nullptr;
    cudaGetSymbolAddress((void**)&qkv_buf, g_qkv);
    cudaGetSymbolAddress((void**)&ao_buf,  g_ao);

    cudaFuncSetAttribute(attn_kernel,
                         cudaFuncAttributeMaxDynamicSharedMemorySize,
                         (int)sizeof(AttnSmem));

    dim3 g1(C3 / 128, N_TOT / 128);
    gemm_tf32<<<g1, 256>>>(feat, qkv_w, qkv_b, qkv_buf, order, nullptr, C3, C_DIM);

    dim3 ga(P_NUM, H_NUM);
    attn_kernel<<<ga, 256, sizeof(AttnSmem)>>>(qkv_buf, gcoord, order, rpe,
                                               ao_buf, rpe_num, pos_b);

    dim3 g3(C_DIM / 128, N_TOT / 128);
    gemm_tf32<<<g3, 256>>>(ao_buf, proj_w, proj_b, out, nullptr, order, C_DIM, C_DIM);
}

// round 6
// speedup vs baseline: 3.2399x; 1.0901x over previous
#include <cuda_runtime.h>
#include <stdint.h>

#define N_TOT   131072
#define C_DIM   512
#define H_NUM   8
#define P_NUM   1024
#define C3      1536
#define RPE_MAX 33

static __device__ float g_qkv[(size_t)N_TOT * C3];
static __device__ float g_ao [(size_t)N_TOT * C_DIM];

// ---------------------------------------------------------------- helpers --
__device__ __forceinline__ uint32_t f2tf32(float x) {
    uint32_t r;
    asm("cvt.rna.tf32.f32 %0, %1;" : "=r"(r) : "f"(x));
    return r;
}
__device__ __forceinline__ uint32_t cvt_reg(uint32_t r) {
    return f2tf32(__uint_as_float(r));
}
__device__ __forceinline__ uint32_t sptr(const void* p) {
    return (uint32_t)__cvta_generic_to_shared(p);
}
__device__ __forceinline__ void ldsm_x4(uint32_t& r0, uint32_t& r1,
                                        uint32_t& r2, uint32_t& r3, uint32_t addr) {
    asm volatile("ldmatrix.sync.aligned.m8n8.x4.shared.b16 {%0,%1,%2,%3}, [%4];"
                 : "=r"(r0), "=r"(r1), "=r"(r2), "=r"(r3) : "r"(addr));
}
__device__ __forceinline__ void mma_tf32(float* d,
                                         uint32_t a0, uint32_t a1, uint32_t a2, uint32_t a3,
                                         uint32_t b0, uint32_t b1)
{
    asm volatile(
        "mma.sync.aligned.m16n8k8.row.col.f32.tf32.tf32.f32 "
        "{%0,%1,%2,%3}, {%4,%5,%6,%7}, {%8,%9}, {%0,%1,%2,%3};"
        : "+f"(d[0]), "+f"(d[1]), "+f"(d[2]), "+f"(d[3])
        : "r"(a0), "r"(a1), "r"(a2), "r"(a3), "r"(b0), "r"(b1));
}
__device__ __forceinline__ void cpa16(uint32_t dst, const float* src) {
    asm volatile("cp.async.cg.shared.global [%0], [%1], 16;"
                 :: "r"(dst), "l"(src) : "memory");
}
__device__ __forceinline__ void cpa_commit() {
    asm volatile("cp.async.commit_group;" ::: "memory");
}
__device__ __forceinline__ void cpa_wait1() {
    asm volatile("cp.async.wait_group 1;" ::: "memory");
}

// ---------------------------------------------------------------------------
// TF32 mma.sync GEMM (NT): out[row(m), j] = sum_c A[arow(m), c]*W[j, c] + b[j]
// Block tile 128m x 256n, BK=16, 8 warps (2m x 4n) of 64x64 warp tiles.
// 3-stage cp.async pipeline; fragments via ldmatrix; cvt.rna after ldmatrix.
// ---------------------------------------------------------------------------
#define LDA      20                 // 16 k-words + 4 pad words
#define A_BYTES  (128 * LDA * 4)    // 10240
#define B_BYTES  (256 * LDA * 4)    // 20480
#define STG      (A_BYTES + B_BYTES)// 30720
#define NSTAGE   3
#define DYN_SMEM (NSTAGE * STG)     // 92160

__global__ __launch_bounds__(256, 1) void gemm_tc(
    const float* __restrict__ A, const float* __restrict__ W,
    const float* __restrict__ bias, float* __restrict__ out,
    const int* __restrict__ gidx, const int* __restrict__ sidx,
    int Ncols, int Kd)
{
    extern __shared__ char dyn[];
    const uint32_t sbase = sptr(dyn);

    const int t = threadIdx.x;
    const int warp = t >> 5;
    const int lane = t & 31;
    const int wm = warp & 1;        // 2 warps over M (64 rows each)
    const int wn = warp >> 1;       // 4 warps over N (64 cols each)
    const int m0 = blockIdx.y * 128;
    const int j0 = blockIdx.x * 256;

    // Fill mapping: thread handles float4 chunk c4 of rows r, r+64 (A) and
    // rows r+64j, j=0..3 (B).
    const int r  = t >> 2;
    const int c4 = t & 3;

    int am0 = m0 + r, am1 = m0 + r + 64;
    if (gidx) { am0 = gidx[am0]; am1 = gidx[am1]; }
    const float* Ag0 = A + (size_t)am0 * Kd + c4 * 4;
    const float* Ag1 = A + (size_t)am1 * Kd + c4 * 4;
    const float* Wg0 = W + (size_t)(j0 + r)       * Kd + c4 * 4;
    const float* Wg1 = W + (size_t)(j0 + r + 64)  * Kd + c4 * 4;
    const float* Wg2 = W + (size_t)(j0 + r + 128) * Kd + c4 * 4;
    const float* Wg3 = W + (size_t)(j0 + r + 192) * Kd + c4 * 4;
    const uint32_t Asw0 = r * 80 + c4 * 16;
    const uint32_t Asw1 = (r + 64) * 80 + c4 * 16;
    const uint32_t Bsw0 = r * 80 + c4 * 16;
    const uint32_t Bsw1 = (r + 64) * 80 + c4 * 16;
    const uint32_t Bsw2 = (r + 128) * 80 + c4 * 16;
    const uint32_t Bsw3 = (r + 192) * 80 + c4 * 16;

#define ISSUE_STAGE(s, kt) do {                                   \
        uint32_t ab_ = sbase + (s) * STG;                         \
        uint32_t bb_ = ab_ + A_BYTES;                             \
        int ko_ = (kt) * 16;                                      \
        cpa16(ab_ + Asw0, Ag0 + ko_);                             \
        cpa16(ab_ + Asw1, Ag1 + ko_);                             \
        cpa16(bb_ + Bsw0, Wg0 + ko_);                             \
        cpa16(bb_ + Bsw1, Wg1 + ko_);                             \
        cpa16(bb_ + Bsw2, Wg2 + ko_);                             \
        cpa16(bb_ + Bsw3, Wg3 + ko_);                             \
    } while (0)

    float acc[4][8][4];
    #pragma unroll
    for (int mt = 0; mt < 4; mt++)
        #pragma unroll
        for (int nt = 0; nt < 8; nt++)
            #pragma unroll
            for (int i = 0; i < 4; i++) acc[mt][nt][i] = 0.f;

    const int iters = Kd >> 4;

    ISSUE_STAGE(0, 0); cpa_commit();
    ISSUE_STAGE(1, 1); cpa_commit();

    // ldmatrix lane-address components (validated in round 4)
    const int a_roff = (lane & 7) + ((lane & 8) ? 8 : 0);
    const int a_coff = (lane & 16) ? 4 : 0;
    const int b_roff = (lane & 7) + ((lane & 16) ? 8 : 0);
    const int b_coff = (lane & 8) ? 4 : 0;

    for (int c = 0; c < iters; c++) {
        const int s = c % NSTAGE;
        cpa_wait1();
        __syncthreads();
        if (c + 2 < iters) ISSUE_STAGE((c + 2) % NSTAGE, c + 2);
        cpa_commit();

        const uint32_t ab = sbase + s * STG;
        const uint32_t bb = ab + A_BYTES;
        #pragma unroll
        for (int ks = 0; ks < 16; ks += 8) {
            uint32_t bf[8][2];
            #pragma unroll
            for (int ntp = 0; ntp < 4; ntp++) {
                uint32_t b0, b1, b2, b3;
                ldsm_x4(b0, b1, b2, b3,
                        bb + ((wn * 64 + ntp * 16 + b_roff) * LDA + ks + b_coff) * 4);
                bf[2*ntp][0]   = cvt_reg(b0);
                bf[2*ntp][1]   = cvt_reg(b1);
                bf[2*ntp+1][0] = cvt_reg(b2);
                bf[2*ntp+1][1] = cvt_reg(b3);
            }
            #pragma unroll
            for (int mt = 0; mt < 4; mt++) {
                uint32_t a0, a1, a2, a3;
                ldsm_x4(a0, a1, a2, a3,
                        ab + ((wm * 64 + mt * 16 + a_roff) * LDA + ks + a_coff) * 4);
                a0 = cvt_reg(a0); a1 = cvt_reg(a1);
                a2 = cvt_reg(a2); a3 = cvt_reg(a3);
                #pragma unroll
                for (int nt = 0; nt < 8; nt++)
                    mma_tf32(acc[mt][nt], a0, a1, a2, a3, bf[nt][0], bf[nt][1]);
            }
        }
        __syncthreads();
    }

    // Epilogue: bias + optional scatter
    const int gr = lane >> 2;
    const int gc = lane & 3;
    #pragma unroll
    for (int mt = 0; mt < 4; mt++) {
        int m_a = m0 + wm * 64 + mt * 16 + gr;
        int m_b = m_a + 8;
        int orow_a = sidx ? sidx[m_a] : m_a;
        int orow_b = sidx ? sidx[m_b] : m_b;
        #pragma unroll
        for (int nt = 0; nt < 8; nt++) {
            int col = j0 + wn * 64 + nt * 8 + gc * 2;
            float b0 = bias[col], b1 = bias[col + 1];
            float2 v0 = make_float2(acc[mt][nt][0] + b0, acc[mt][nt][1] + b1);
            float2 v1 = make_float2(acc[mt][nt][2] + b0, acc[mt][nt][3] + b1);
            *(float2*)(out + (size_t)orow_a * Ncols + col) = v0;
            *(float2*)(out + (size_t)orow_b * Ncols + col) = v1;
        }
    }
#undef ISSUE_STAGE
}

// ---------------------------------------------------------------------------
// Attention (tf32 mma.sync): one block per (patch, head), 8 warps. (Round-4)
// ---------------------------------------------------------------------------
#define LQ 68
#define LP 132

struct __align__(16) AttnSmem {
    uint32_t qs[128 * LQ];
    uint32_t ks[128 * LQ];
    uint32_t vt[64 * LP];
    float    Ps[128 * LP];
    float    rowsum[128];
    int      cx[128], cy[128], cz[128];
    float    rp[3][RPE_MAX];
};

__global__ __launch_bounds__(256) void attn_kernel(
    const float* __restrict__ qkv, const int* __restrict__ gcoord,
    const int* __restrict__ order, const float* __restrict__ rpe,
    float* __restrict__ out, int rpe_num, int pos_b)
{
    extern __shared__ char smem_raw[];
    AttnSmem& sm = *reinterpret_cast<AttnSmem*>(smem_raw);
    const int p = blockIdx.x;
    const int h = blockIdx.y;
    const int t = threadIdx.x;
    const int lane = t & 31;
    const int warp = t >> 5;

    for (int f = t; f < 2048; f += 256) {
        int i  = f >> 4;
        int dg = (f & 15) * 4;
        const float* base = qkv + (size_t)(p * 128 + i) * C3 + h * 64 + dg;
        float4 qv = *(const float4*)(base);
        float4 kv = *(const float4*)(base + 512);
        float4 vv = *(const float4*)(base + 1024);
        uint32_t* qp = &sm.qs[i * LQ + dg];
        uint32_t* kp = &sm.ks[i * LQ + dg];
        qp[0]=f2tf32(qv.x); qp[1]=f2tf32(qv.y); qp[2]=f2tf32(qv.z); qp[3]=f2tf32(qv.w);
        kp[0]=f2tf32(kv.x); kp[1]=f2tf32(kv.y); kp[2]=f2tf32(kv.z); kp[3]=f2tf32(kv.w);
        sm.vt[(dg + 0) * LP + i] = f2tf32(vv.x);
        sm.vt[(dg + 1) * LP + i] = f2tf32(vv.y);
        sm.vt[(dg + 2) * LP + i] = f2tf32(vv.z);
        sm.vt[(dg + 3) * LP + i] = f2tf32(vv.w);
    }
    if (t < 128) {
        int gi = order[p * 128 + t];
        sm.cx[t] = gcoord[gi * 3 + 0];
        sm.cy[t] = gcoord[gi * 3 + 1];
        sm.cz[t] = gcoord[gi * 3 + 2];
    }
    if (t < 3 * rpe_num) {
        sm.rp[t / rpe_num][t % rpe_num] = rpe[t * H_NUM + h];
    }
    __syncthreads();

    const int m0w = warp * 16;
    const int a_roff = (lane & 7) + ((lane & 8) ? 8 : 0);
    const int a_coff = (lane & 16) ? 4 : 0;
    const int b_roff = (lane & 7) + ((lane & 16) ? 8 : 0);
    const int b_coff = (lane & 8) ? 4 : 0;
    const int gr = lane >> 2;
    const int gc = lane & 3;

    float acc[16][4];
    #pragma unroll
    for (int nt = 0; nt < 16; nt++)
        #pragma unroll
        for (int i = 0; i < 4; i++) acc[nt][i] = 0.f;

    #pragma unroll
    for (int d0 = 0; d0 < 64; d0 += 8) {
        uint32_t a0, a1, a2, a3;
        ldsm_x4(a0, a1, a2, a3, sptr(&sm.qs[(m0w + a_roff) * LQ + d0 + a_coff]));
        #pragma unroll
        for (int ntp = 0; ntp < 8; ntp++) {
            uint32_t b0, b1, c0, c1;
            ldsm_x4(b0, b1, c0, c1, sptr(&sm.ks[(ntp * 16 + b_roff) * LQ + d0 + b_coff]));
            mma_tf32(acc[2*ntp],     a0, a1, a2, a3, b0, b1);
            mma_tf32(acc[2*ntp + 1], a0, a1, a2, a3, c0, c1);
        }
    }

    const float scale = 0.125f;
    const int i0 = m0w + gr, i1 = i0 + 8;
    const int x0 = sm.cx[i0], y0 = sm.cy[i0], z0 = sm.cz[i0];
    const int x1 = sm.cx[i1], y1 = sm.cy[i1], z1 = sm.cz[i1];
    #pragma unroll
    for (int nt = 0; nt < 16; nt++) {
        int j0c = nt * 8 + gc * 2;
        #pragma unroll
        for (int jj = 0; jj < 2; jj++) {
            int j = j0c + jj;
            int xj = sm.cx[j], yj = sm.cy[j], zj = sm.cz[j];
            int dx0 = min(max(x0 - xj, -pos_b), pos_b) + pos_b;
            int dy0 = min(max(y0 - yj, -pos_b), pos_b) + pos_b;
            int dz0 = min(max(z0 - zj, -pos_b), pos_b) + pos_b;
            int dx1 = min(max(x1 - xj, -pos_b), pos_b) + pos_b;
            int dy1 = min(max(y1 - yj, -pos_b), pos_b) + pos_b;
            int dz1 = min(max(z1 - zj, -pos_b), pos_b) + pos_b;
            float bias0 = sm.rp[0][dx0] + sm.rp[1][dy0] + sm.rp[2][dz0];
            float bias1 = sm.rp[0][dx1] + sm.rp[1][dy1] + sm.rp[2][dz1];
            sm.Ps[i0 * LP + j] = acc[nt][jj]     * scale + bias0;
            sm.Ps[i1 * LP + j] = acc[nt][jj + 2] * scale + bias1;
        }
    }
    __syncwarp();

    #pragma unroll 2
    for (int rr = 0; rr < 16; rr++) {
        int row = m0w + rr;
        float v0 = sm.Ps[row * LP + lane];
        float v1 = sm.Ps[row * LP + lane + 32];
        float v2 = sm.Ps[row * LP + lane + 64];
        float v3 = sm.Ps[row * LP + lane + 96];
        float mx = fmaxf(fmaxf(v0, v1), fmaxf(v2, v3));
        #pragma unroll
        for (int s = 16; s > 0; s >>= 1)
            mx = fmaxf(mx, __shfl_xor_sync(0xffffffffu, mx, s));
        float e0 = __expf(v0 - mx), e1 = __expf(v1 - mx);
        float e2 = __expf(v2 - mx), e3 = __expf(v3 - mx);
        float s4 = (e0 + e1) + (e2 + e3);
        #pragma unroll
        for (int s = 16; s > 0; s >>= 1)
            s4 += __shfl_xor_sync(0xffffffffu, s4, s);
        sm.Ps[row * LP + lane]      = __uint_as_float(f2tf32(e0));
        sm.Ps[row * LP + lane + 32] = __uint_as_float(f2tf32(e1));
        sm.Ps[row * LP + lane + 64] = __uint_as_float(f2tf32(e2));
        sm.Ps[row * LP + lane + 96] = __uint_as_float(f2tf32(e3));
        if (lane == 0) sm.rowsum[row] = s4;
    }
    __syncwarp();

    float o[8][4];
    #pragma unroll
    for (int nt = 0; nt < 8; nt++)
        #pragma unroll
        for (int i = 0; i < 4; i++) o[nt][i] = 0.f;

    const uint32_t* Pu = (const uint32_t*)sm.Ps;
    #pragma unroll
    for (int mm = 0; mm < 128; mm += 8) {
        uint32_t a0, a1, a2, a3;
        ldsm_x4(a0, a1, a2, a3, sptr(&Pu[(m0w + a_roff) * LP + mm + a_coff]));
        #pragma unroll
        for (int ntp = 0; ntp < 4; ntp++) {
            uint32_t b0, b1, c0, c1;
            ldsm_x4(b0, b1, c0, c1, sptr(&sm.vt[(ntp * 16 + b_roff) * LP + mm + b_coff]));
            mma_tf32(o[2*ntp],     a0, a1, a2, a3, b0, b1);
            mma_tf32(o[2*ntp + 1], a0, a1, a2, a3, c0, c1);
        }
    }

    const float inv0 = 1.f / sm.rowsum[i0];
    const float inv1 = 1.f / sm.rowsum[i1];
    #pragma unroll
    for (int nt = 0; nt < 8; nt++) {
        int col = h * 64 + nt * 8 + gc * 2;
        float2 w0 = make_float2(o[nt][0] * inv0, o[nt][1] * inv0);
        float2 w1 = make_float2(o[nt][2] * inv1, o[nt][3] * inv1);
        *(float2*)(out + (size_t)(p * 128 + i0) * C_DIM + col) = w0;
        *(float2*)(out + (size_t)(p * 128 + i1) * C_DIM + col) = w1;
    }
}

// ---------------------------------------------------------------------------
extern "C" void kernel_launch(void* const* d_in, const int* in_sizes, int n_in,
                              void* d_out, int out_size)
{
    const float* feat   = (const float*)d_in[0];
    const int*   gcoord = (const int*)  d_in[1];
    const int*   order  = (const int*)  d_in[2];
    const float* qkv_w  = (const float*)d_in[4];
    const float* qkv_b  = (const float*)d_in[5];
    const float* proj_w = (const float*)d_in[6];
    const float* proj_b = (const float*)d_in[7];
    const float* rpe    = (const float*)d_in[8];
    float* out = (float*)d_out;

    int rpe_num = in_sizes[8] / (3 * H_NUM);   // 31 (ref comment saying 33 is wrong)
    if (rpe_num > RPE_MAX) rpe_num = RPE_MAX;
    int pos_b = (rpe_num - 1) / 2;

    float *qkv_buf = nullptr, *ao_buf = nullptr;
    cudaGetSymbolAddress((void**)&qkv_buf, g_qkv);
    cudaGetSymbolAddress((void**)&ao_buf,  g_ao);

    cudaFuncSetAttribute(gemm_tc,
                         cudaFuncAttributeMaxDynamicSharedMemorySize, DYN_SMEM);
    cudaFuncSetAttribute(attn_kernel,
                         cudaFuncAttributeMaxDynamicSharedMemorySize,
                         (int)sizeof(AttnSmem));

    // Stage 1: gather + QKV projection
    dim3 g1(C3 / 256, N_TOT / 128);
    gemm_tc<<<g1, 256, DYN_SMEM>>>(feat, qkv_w, qkv_b, qkv_buf, order, nullptr,
                                   C3, C_DIM);

    // Stage 2: per-(patch, head) attention with RPE
    dim3 ga(P_NUM, H_NUM);
    attn_kernel<<<ga, 256, sizeof(AttnSmem)>>>(qkv_buf, gcoord, order, rpe,
                                               ao_buf, rpe_num, pos_b);

    // Stage 3: output projection + scatter
    dim3 g3(C_DIM / 256, N_TOT / 128);
    gemm_tc<<<g3, 256, DYN_SMEM>>>(ao_buf, proj_w, proj_b, out, nullptr, order,
                                   C_DIM, C_DIM);
}

// round 7
// speedup vs baseline: 3.8397x; 1.1851x over previous
#include <cuda_runtime.h>
#include <stdint.h>

#define N_TOT   131072
#define C_DIM   512
#define H_NUM   8
#define P_NUM   1024
#define C3      1536
#define RPE_MAX 33

static __device__ float    g_qkv [(size_t)N_TOT * C3];     // stage1 out (fp32)
static __device__ float    g_ao  [(size_t)N_TOT * C_DIM];  // attn out (tf32-rounded)
static __device__ uint32_t g_gath[(size_t)N_TOT * C_DIM];  // feat[order] as tf32
static __device__ uint32_t g_w1  [(size_t)C3 * C_DIM];     // qkv_w tf32
static __device__ uint32_t g_w3  [(size_t)C_DIM * C_DIM];  // proj_w tf32

// ---------------------------------------------------------------- helpers --
__device__ __forceinline__ uint32_t f2tf32(float x) {
    uint32_t r;
    asm("cvt.rna.tf32.f32 %0, %1;" : "=r"(r) : "f"(x));
    return r;
}
__device__ __forceinline__ uint32_t sptr(const void* p) {
    return (uint32_t)__cvta_generic_to_shared(p);
}
__device__ __forceinline__ void ldsm_x4(uint32_t& r0, uint32_t& r1,
                                        uint32_t& r2, uint32_t& r3, uint32_t addr) {
    asm volatile("ldmatrix.sync.aligned.m8n8.x4.shared.b16 {%0,%1,%2,%3}, [%4];"
                 : "=r"(r0), "=r"(r1), "=r"(r2), "=r"(r3) : "r"(addr));
}
__device__ __forceinline__ void mma_tf32(float* d,
                                         uint32_t a0, uint32_t a1, uint32_t a2, uint32_t a3,
                                         uint32_t b0, uint32_t b1)
{
    asm volatile(
        "mma.sync.aligned.m16n8k8.row.col.f32.tf32.tf32.f32 "
        "{%0,%1,%2,%3}, {%4,%5,%6,%7}, {%8,%9}, {%0,%1,%2,%3};"
        : "+f"(d[0]), "+f"(d[1]), "+f"(d[2]), "+f"(d[3])
        : "r"(a0), "r"(a1), "r"(a2), "r"(a3), "r"(b0), "r"(b1));
}
__device__ __forceinline__ void cpa16(uint32_t dst, const float* src) {
    asm volatile("cp.async.cg.shared.global [%0], [%1], 16;"
                 :: "r"(dst), "l"(src) : "memory");
}
__device__ __forceinline__ void cpa_commit() {
    asm volatile("cp.async.commit_group;" ::: "memory");
}
__device__ __forceinline__ void cpa_wait1() {
    asm volatile("cp.async.wait_group 1;" ::: "memory");
}

// ---------------------------------------------------------------------------
// Pre-pass: gather + fp32->tf32 round (feat[order] -> g_gath)
// ---------------------------------------------------------------------------
__global__ __launch_bounds__(256) void gather_cvt(
    const float* __restrict__ feat, const int* __restrict__ order,
    uint32_t* __restrict__ outb)
{
    size_t idx = (size_t)blockIdx.x * 256 + threadIdx.x;   // one float4 each
    int m = (int)(idx >> 7);               // 128 float4 per 512-col row
    int c = (int)(idx & 127) << 2;
    int src = order[m];
    float4 v = *(const float4*)(feat + (size_t)src * C_DIM + c);
    uint4 o;
    o.x = f2tf32(v.x); o.y = f2tf32(v.y); o.z = f2tf32(v.z); o.w = f2tf32(v.w);
    *(uint4*)(outb + idx * 4) = o;
}

__global__ __launch_bounds__(256) void cvt_only(
    const float* __restrict__ in, uint32_t* __restrict__ outb)
{
    size_t idx = (size_t)blockIdx.x * 256 + threadIdx.x;
    float4 v = *(const float4*)(in + idx * 4);
    uint4 o;
    o.x = f2tf32(v.x); o.y = f2tf32(v.y); o.z = f2tf32(v.z); o.w = f2tf32(v.w);
    *(uint4*)(outb + idx * 4) = o;
}

// ---------------------------------------------------------------------------
// TF32 mma.sync GEMM (NT), inputs ALREADY tf32-rounded (no cvt in loop).
// Block tile 128m x 256n, BK=16, 8 warps (2m x 4n) of 64x64, 3-stage cp.async.
// ---------------------------------------------------------------------------
#define LDA      20
#define A_BYTES  (128 * LDA * 4)
#define B_BYTES  (256 * LDA * 4)
#define STG      (A_BYTES + B_BYTES)
#define NSTAGE   3
#define DYN_SMEM (NSTAGE * STG)

__global__ __launch_bounds__(256, 1) void gemm_tc(
    const float* __restrict__ A, const float* __restrict__ W,
    const float* __restrict__ bias, float* __restrict__ out,
    const int* __restrict__ sidx, int Ncols, int Kd)
{
    extern __shared__ char dyn[];
    const uint32_t sbase = sptr(dyn);

    const int t = threadIdx.x;
    const int warp = t >> 5;
    const int lane = t & 31;
    const int wm = warp & 1;
    const int wn = warp >> 1;
    const int m0 = blockIdx.y * 128;
    const int j0 = blockIdx.x * 256;

    const int r  = t >> 2;
    const int c4 = t & 3;

    const float* Ag0 = A + (size_t)(m0 + r)      * Kd + c4 * 4;
    const float* Ag1 = A + (size_t)(m0 + r + 64) * Kd + c4 * 4;
    const float* Wg0 = W + (size_t)(j0 + r)       * Kd + c4 * 4;
    const float* Wg1 = W + (size_t)(j0 + r + 64)  * Kd + c4 * 4;
    const float* Wg2 = W + (size_t)(j0 + r + 128) * Kd + c4 * 4;
    const float* Wg3 = W + (size_t)(j0 + r + 192) * Kd + c4 * 4;
    const uint32_t Asw0 = r * 80 + c4 * 16;
    const uint32_t Asw1 = (r + 64) * 80 + c4 * 16;
    const uint32_t Bsw1 = (r + 64) * 80 + c4 * 16;
    const uint32_t Bsw2 = (r + 128) * 80 + c4 * 16;
    const uint32_t Bsw3 = (r + 192) * 80 + c4 * 16;

#define ISSUE_STAGE(s, kt) do {                                   \
        uint32_t ab_ = sbase + (s) * STG;                         \
        uint32_t bb_ = ab_ + A_BYTES;                             \
        int ko_ = (kt) * 16;                                      \
        cpa16(ab_ + Asw0, Ag0 + ko_);                             \
        cpa16(ab_ + Asw1, Ag1 + ko_);                             \
        cpa16(bb_ + Asw0, Wg0 + ko_);                             \
        cpa16(bb_ + Bsw1, Wg1 + ko_);                             \
        cpa16(bb_ + Bsw2, Wg2 + ko_);                             \
        cpa16(bb_ + Bsw3, Wg3 + ko_);                             \
    } while (0)

    float acc[4][8][4];
    #pragma unroll
    for (int mt = 0; mt < 4; mt++)
        #pragma unroll
        for (int nt = 0; nt < 8; nt++)
            #pragma unroll
            for (int i = 0; i < 4; i++) acc[mt][nt][i] = 0.f;

    const int iters = Kd >> 4;

    ISSUE_STAGE(0, 0); cpa_commit();
    ISSUE_STAGE(1, 1); cpa_commit();

    const int a_roff = (lane & 7) + ((lane & 8) ? 8 : 0);
    const int a_coff = (lane & 16) ? 4 : 0;
    const int b_roff = (lane & 7) + ((lane & 16) ? 8 : 0);
    const int b_coff = (lane & 8) ? 4 : 0;

    for (int c = 0; c < iters; c++) {
        const int s = c % NSTAGE;
        cpa_wait1();
        __syncthreads();
        if (c + 2 < iters) ISSUE_STAGE((c + 2) % NSTAGE, c + 2);
        cpa_commit();

        const uint32_t ab = sbase + s * STG;
        const uint32_t bb = ab + A_BYTES;
        #pragma unroll
        for (int ks = 0; ks < 16; ks += 8) {
            uint32_t bf[8][2];
            #pragma unroll
            for (int ntp = 0; ntp < 4; ntp++) {
                ldsm_x4(bf[2*ntp][0], bf[2*ntp][1], bf[2*ntp+1][0], bf[2*ntp+1][1],
                        bb + ((wn * 64 + ntp * 16 + b_roff) * LDA + ks + b_coff) * 4);
            }
            #pragma unroll
            for (int mt = 0; mt < 4; mt++) {
                uint32_t a0, a1, a2, a3;
                ldsm_x4(a0, a1, a2, a3,
                        ab + ((wm * 64 + mt * 16 + a_roff) * LDA + ks + a_coff) * 4);
                #pragma unroll
                for (int nt = 0; nt < 8; nt++)
                    mma_tf32(acc[mt][nt], a0, a1, a2, a3, bf[nt][0], bf[nt][1]);
            }
        }
        __syncthreads();
    }

    const int gr = lane >> 2;
    const int gc = lane & 3;
    #pragma unroll
    for (int mt = 0; mt < 4; mt++) {
        int m_a = m0 + wm * 64 + mt * 16 + gr;
        int m_b = m_a + 8;
        int orow_a = sidx ? sidx[m_a] : m_a;
        int orow_b = sidx ? sidx[m_b] : m_b;
        #pragma unroll
        for (int nt = 0; nt < 8; nt++) {
            int col = j0 + wn * 64 + nt * 8 + gc * 2;
            float b0 = bias[col], b1 = bias[col + 1];
            float2 v0 = make_float2(acc[mt][nt][0] + b0, acc[mt][nt][1] + b1);
            float2 v1 = make_float2(acc[mt][nt][2] + b0, acc[mt][nt][3] + b1);
            *(float2*)(out + (size_t)orow_a * Ncols + col) = v0;
            *(float2*)(out + (size_t)orow_b * Ncols + col) = v1;
        }
    }
#undef ISSUE_STAGE
}

// ---------------------------------------------------------------------------
// Attention v2: register softmax (no Ps smem), 2 CTAs/SM.
// One block per (patch, head), 8 warps; warp w owns rows 16w..16w+15.
// Output written tf32-rounded (stage 3 consumes raw).
// ---------------------------------------------------------------------------
#define LQ 68
#define LP 132

struct __align__(16) AttnSmem {
    uint32_t qs[128 * LQ];
    uint32_t ks[128 * LQ];
    uint32_t vt[64 * LP];
    int      cx[128], cy[128], cz[128];
    float    rp[3][RPE_MAX];
};

__global__ __launch_bounds__(256, 2) void attn_kernel(
    const float* __restrict__ qkv, const int* __restrict__ gcoord,
    const int* __restrict__ order, const float* __restrict__ rpe,
    float* __restrict__ out, int rpe_num, int pos_b)
{
    extern __shared__ char smem_raw[];
    AttnSmem& sm = *reinterpret_cast<AttnSmem*>(smem_raw);
    const int p = blockIdx.x;
    const int h = blockIdx.y;
    const int t = threadIdx.x;
    const int lane = t & 31;
    const int warp = t >> 5;

    for (int f = t; f < 2048; f += 256) {
        int i  = f >> 4;
        int dg = (f & 15) * 4;
        const float* base = qkv + (size_t)(p * 128 + i) * C3 + h * 64 + dg;
        float4 qv = *(const float4*)(base);
        float4 kv = *(const float4*)(base + 512);
        float4 vv = *(const float4*)(base + 1024);
        uint32_t* qp = &sm.qs[i * LQ + dg];
        uint32_t* kp = &sm.ks[i * LQ + dg];
        qp[0]=f2tf32(qv.x); qp[1]=f2tf32(qv.y); qp[2]=f2tf32(qv.z); qp[3]=f2tf32(qv.w);
        kp[0]=f2tf32(kv.x); kp[1]=f2tf32(kv.y); kp[2]=f2tf32(kv.z); kp[3]=f2tf32(kv.w);
        sm.vt[(dg + 0) * LP + i] = f2tf32(vv.x);
        sm.vt[(dg + 1) * LP + i] = f2tf32(vv.y);
        sm.vt[(dg + 2) * LP + i] = f2tf32(vv.z);
        sm.vt[(dg + 3) * LP + i] = f2tf32(vv.w);
    }
    if (t < 128) {
        int gi = order[p * 128 + t];
        sm.cx[t] = gcoord[gi * 3 + 0];
        sm.cy[t] = gcoord[gi * 3 + 1];
        sm.cz[t] = gcoord[gi * 3 + 2];
    }
    if (t < 3 * rpe_num) {
        sm.rp[t / rpe_num][t % rpe_num] = rpe[t * H_NUM + h];
    }
    __syncthreads();

    const int m0w = warp * 16;
    const int a_roff = (lane & 7) + ((lane & 8) ? 8 : 0);
    const int a_coff = (lane & 16) ? 4 : 0;
    const int b_roff = (lane & 7) + ((lane & 16) ? 8 : 0);
    const int b_coff = (lane & 8) ? 4 : 0;
    const int gr = lane >> 2;
    const int gc = lane & 3;

    // ---- QK^T: acc[nt] = S(i0, j), S(i0, j+1), S(i1, j), S(i1, j+1) ----
    float acc[16][4];
    #pragma unroll
    for (int nt = 0; nt < 16; nt++)
        #pragma unroll
        for (int i = 0; i < 4; i++) acc[nt][i] = 0.f;

    #pragma unroll
    for (int d0 = 0; d0 < 64; d0 += 8) {
        uint32_t a0, a1, a2, a3;
        ldsm_x4(a0, a1, a2, a3, sptr(&sm.qs[(m0w + a_roff) * LQ + d0 + a_coff]));
        #pragma unroll
        for (int ntp = 0; ntp < 8; ntp++) {
            uint32_t b0, b1, c0, c1;
            ldsm_x4(b0, b1, c0, c1, sptr(&sm.ks[(ntp * 16 + b_roff) * LQ + d0 + b_coff]));
            mma_tf32(acc[2*ntp],     a0, a1, a2, a3, b0, b1);
            mma_tf32(acc[2*ntp + 1], a0, a1, a2, a3, c0, c1);
        }
    }

    // ---- scale + RPE bias (registers) ----
    const float scale = 0.125f;
    const int i0 = m0w + gr, i1 = i0 + 8;
    const int x0 = sm.cx[i0], y0 = sm.cy[i0], z0 = sm.cz[i0];
    const int x1 = sm.cx[i1], y1 = sm.cy[i1], z1 = sm.cz[i1];
    #pragma unroll
    for (int nt = 0; nt < 16; nt++) {
        #pragma unroll
        for (int jj = 0; jj < 2; jj++) {
            int j = nt * 8 + gc * 2 + jj;
            int xj = sm.cx[j], yj = sm.cy[j], zj = sm.cz[j];
            int dx0 = min(max(x0 - xj, -pos_b), pos_b) + pos_b;
            int dy0 = min(max(y0 - yj, -pos_b), pos_b) + pos_b;
            int dz0 = min(max(z0 - zj, -pos_b), pos_b) + pos_b;
            int dx1 = min(max(x1 - xj, -pos_b), pos_b) + pos_b;
            int dy1 = min(max(y1 - yj, -pos_b), pos_b) + pos_b;
            int dz1 = min(max(z1 - zj, -pos_b), pos_b) + pos_b;
            acc[nt][jj]     = acc[nt][jj]     * scale
                            + sm.rp[0][dx0] + sm.rp[1][dy0] + sm.rp[2][dz0];
            acc[nt][jj + 2] = acc[nt][jj + 2] * scale
                            + sm.rp[0][dx1] + sm.rp[1][dy1] + sm.rp[2][dz1];
        }
    }

    // ---- register softmax (rows i0, i1 spread over the 4 quad lanes) ----
    float mx0 = -1e30f, mx1 = -1e30f;
    #pragma unroll
    for (int nt = 0; nt < 16; nt++) {
        mx0 = fmaxf(mx0, fmaxf(acc[nt][0], acc[nt][1]));
        mx1 = fmaxf(mx1, fmaxf(acc[nt][2], acc[nt][3]));
    }
    mx0 = fmaxf(mx0, __shfl_xor_sync(0xffffffffu, mx0, 1));
    mx0 = fmaxf(mx0, __shfl_xor_sync(0xffffffffu, mx0, 2));
    mx1 = fmaxf(mx1, __shfl_xor_sync(0xffffffffu, mx1, 1));
    mx1 = fmaxf(mx1, __shfl_xor_sync(0xffffffffu, mx1, 2));

    float s0 = 0.f, s1 = 0.f;
    #pragma unroll
    for (int nt = 0; nt < 16; nt++) {
        acc[nt][0] = __expf(acc[nt][0] - mx0);
        acc[nt][1] = __expf(acc[nt][1] - mx0);
        acc[nt][2] = __expf(acc[nt][2] - mx1);
        acc[nt][3] = __expf(acc[nt][3] - mx1);
        s0 += acc[nt][0] + acc[nt][1];
        s1 += acc[nt][2] + acc[nt][3];
    }
    s0 += __shfl_xor_sync(0xffffffffu, s0, 1);
    s0 += __shfl_xor_sync(0xffffffffu, s0, 2);
    s1 += __shfl_xor_sync(0xffffffffu, s1, 1);
    s1 += __shfl_xor_sync(0xffffffffu, s1, 2);

    // ---- PV: A fragments from registers via quad shuffles ----
    float o[8][4];
    #pragma unroll
    for (int nt = 0; nt < 8; nt++)
        #pragma unroll
        for (int i = 0; i < 4; i++) o[nt][i] = 0.f;

    const int base_l = lane & ~3;
    const int src_lo = base_l | (gc >> 1);
    const int src_hi = src_lo + 2;
    const bool odd = (gc & 1);

    #pragma unroll
    for (int kg = 0; kg < 16; kg++) {
        // row i0: cols kg*8 + {gc, gc+4}; row i1 same.
        float p00 = __shfl_sync(0xffffffffu, acc[kg][0], src_lo);
        float p01 = __shfl_sync(0xffffffffu, acc[kg][1], src_lo);
        float p02 = __shfl_sync(0xffffffffu, acc[kg][0], src_hi);
        float p03 = __shfl_sync(0xffffffffu, acc[kg][1], src_hi);
        float p10 = __shfl_sync(0xffffffffu, acc[kg][2], src_lo);
        float p11 = __shfl_sync(0xffffffffu, acc[kg][3], src_lo);
        float p12 = __shfl_sync(0xffffffffu, acc[kg][2], src_hi);
        float p13 = __shfl_sync(0xffffffffu, acc[kg][3], src_hi);
        uint32_t a0 = f2tf32(odd ? p01 : p00);
        uint32_t a1 = f2tf32(odd ? p11 : p10);
        uint32_t a2 = f2tf32(odd ? p03 : p02);
        uint32_t a3 = f2tf32(odd ? p13 : p12);
        #pragma unroll
        for (int ntp = 0; ntp < 4; ntp++) {
            uint32_t b0, b1, c0, c1;
            ldsm_x4(b0, b1, c0, c1,
                    sptr(&sm.vt[(ntp * 16 + b_roff) * LP + kg * 8 + b_coff]));
            mma_tf32(o[2*ntp],     a0, a1, a2, a3, b0, b1);
            mma_tf32(o[2*ntp + 1], a0, a1, a2, a3, c0, c1);
        }
    }

    // ---- normalize, round to tf32 (stage-3 input), store ----
    const float inv0 = 1.f / s0;
    const float inv1 = 1.f / s1;
    #pragma unroll
    for (int nt = 0; nt < 8; nt++) {
        int col = h * 64 + nt * 8 + gc * 2;
        float2 w0, w1;
        w0.x = __uint_as_float(f2tf32(o[nt][0] * inv0));
        w0.y = __uint_as_float(f2tf32(o[nt][1] * inv0));
        w1.x = __uint_as_float(f2tf32(o[nt][2] * inv1));
        w1.y = __uint_as_float(f2tf32(o[nt][3] * inv1));
        *(float2*)(out + (size_t)(p * 128 + i0) * C_DIM + col) = w0;
        *(float2*)(out + (size_t)(p * 128 + i1) * C_DIM + col) = w1;
    }
}

// ---------------------------------------------------------------------------
extern "C" void kernel_launch(void* const* d_in, const int* in_sizes, int n_in,
                              void* d_out, int out_size)
{
    const float* feat   = (const float*)d_in[0];
    const int*   gcoord = (const int*)  d_in[1];
    const int*   order  = (const int*)  d_in[2];
    const float* qkv_w  = (const float*)d_in[4];
    const float* qkv_b  = (const float*)d_in[5];
    const float* proj_w = (const float*)d_in[6];
    const float* proj_b = (const float*)d_in[7];
    const float* rpe    = (const float*)d_in[8];
    float* out = (float*)d_out;

    int rpe_num = in_sizes[8] / (3 * H_NUM);   // 31 (ref comment is wrong)
    if (rpe_num > RPE_MAX) rpe_num = RPE_MAX;
    int pos_b = (rpe_num - 1) / 2;

    float *qkv_buf = nullptr, *ao_buf = nullptr;
    uint32_t *gath = nullptr, *w1 = nullptr, *w3 = nullptr;
    cudaGetSymbolAddress((void**)&qkv_buf, g_qkv);
    cudaGetSymbolAddress((void**)&ao_buf,  g_ao);
    cudaGetSymbolAddress((void**)&gath,    g_gath);
    cudaGetSymbolAddress((void**)&w1,      g_w1);
    cudaGetSymbolAddress((void**)&w3,      g_w3);

    cudaFuncSetAttribute(gemm_tc,
                         cudaFuncAttributeMaxDynamicSharedMemorySize, DYN_SMEM);
    cudaFuncSetAttribute(attn_kernel,
                         cudaFuncAttributeMaxDynamicSharedMemorySize,
                         (int)sizeof(AttnSmem));

    // Pre-pass: gather+cvt feat; cvt weights
    gather_cvt<<<(N_TOT * (C_DIM / 4)) / 256, 256>>>(feat, order, gath);
    cvt_only<<<(C3 * C_DIM / 4) / 256, 256>>>(qkv_w, w1);
    cvt_only<<<(C_DIM * C_DIM / 4) / 256, 256>>>(proj_w, w3);

    // Stage 1: QKV projection (tf32 inputs, no gather needed)
    dim3 g1(C3 / 256, N_TOT / 128);
    gemm_tc<<<g1, 256, DYN_SMEM>>>((const float*)gath, (const float*)w1,
                                   qkv_b, qkv_buf, nullptr, C3, C_DIM);

    // Stage 2: attention (writes tf32-rounded output)
    dim3 ga(P_NUM, H_NUM);
    attn_kernel<<<ga, 256, sizeof(AttnSmem)>>>(qkv_buf, gcoord, order, rpe,
                                               ao_buf, rpe_num, pos_b);

    // Stage 3: output projection + scatter
    dim3 g3(C_DIM / 256, N_TOT / 128);
    gemm_tc<<<g3, 256, DYN_SMEM>>>((const float*)ao_buf, (const float*)w3,
                                   proj_b, out, order, C_DIM, C_DIM);
}

// round 8
// speedup vs baseline: 3.8634x; 1.0062x over previous
#include <cuda_runtime.h>
#include <stdint.h>

#define N_TOT   131072
#define C_DIM   512
#define H_NUM   8
#define P_NUM   1024
#define C3      1536
#define RPE_MAX 33

static __device__ float    g_qkv [(size_t)N_TOT * C3];     // stage1 out (fp32)
static __device__ float    g_ao  [(size_t)N_TOT * C_DIM];  // attn out (tf32-rounded)
static __device__ uint32_t g_gath[(size_t)N_TOT * C_DIM];  // feat[order] as tf32
static __device__ uint32_t g_w1  [(size_t)C3 * C_DIM];     // qkv_w tf32
static __device__ uint32_t g_w3  [(size_t)C_DIM * C_DIM];  // proj_w tf32

// ---------------------------------------------------------------- helpers --
__device__ __forceinline__ uint32_t f2tf32(float x) {
    uint32_t r;
    asm("cvt.rna.tf32.f32 %0, %1;" : "=r"(r) : "f"(x));
    return r;
}
__device__ __forceinline__ uint32_t sptr(const void* p) {
    return (uint32_t)__cvta_generic_to_shared(p);
}
__device__ __forceinline__ void ldsm_x4(uint32_t& r0, uint32_t& r1,
                                        uint32_t& r2, uint32_t& r3, uint32_t addr) {
    asm volatile("ldmatrix.sync.aligned.m8n8.x4.shared.b16 {%0,%1,%2,%3}, [%4];"
                 : "=r"(r0), "=r"(r1), "=r"(r2), "=r"(r3) : "r"(addr));
}
__device__ __forceinline__ void mma_tf32(float* d,
                                         uint32_t a0, uint32_t a1, uint32_t a2, uint32_t a3,
                                         uint32_t b0, uint32_t b1)
{
    asm volatile(
        "mma.sync.aligned.m16n8k8.row.col.f32.tf32.tf32.f32 "
        "{%0,%1,%2,%3}, {%4,%5,%6,%7}, {%8,%9}, {%0,%1,%2,%3};"
        : "+f"(d[0]), "+f"(d[1]), "+f"(d[2]), "+f"(d[3])
        : "r"(a0), "r"(a1), "r"(a2), "r"(a3), "r"(b0), "r"(b1));
}
__device__ __forceinline__ void cpa16(uint32_t dst, const float* src) {
    asm volatile("cp.async.cg.shared.global [%0], [%1], 16;"
                 :: "r"(dst), "l"(src) : "memory");
}
__device__ __forceinline__ void cpa_commit() {
    asm volatile("cp.async.commit_group;" ::: "memory");
}
__device__ __forceinline__ void cpa_wait1() {
    asm volatile("cp.async.wait_group 1;" ::: "memory");
}

// ---------------------------------------------------------------------------
// Pre-pass: gather + fp32->tf32 round (feat[order] -> g_gath); weight cvt
// ---------------------------------------------------------------------------
__global__ __launch_bounds__(256) void gather_cvt(
    const float* __restrict__ feat, const int* __restrict__ order,
    uint32_t* __restrict__ outb)
{
    size_t idx = (size_t)blockIdx.x * 256 + threadIdx.x;
    int m = (int)(idx >> 7);
    int c = (int)(idx & 127) << 2;
    int src = order[m];
    float4 v = *(const float4*)(feat + (size_t)src * C_DIM + c);
    uint4 o;
    o.x = f2tf32(v.x); o.y = f2tf32(v.y); o.z = f2tf32(v.z); o.w = f2tf32(v.w);
    *(uint4*)(outb + idx * 4) = o;
}

__global__ __launch_bounds__(256) void cvt_only(
    const float* __restrict__ in, uint32_t* __restrict__ outb)
{
    size_t idx = (size_t)blockIdx.x * 256 + threadIdx.x;
    float4 v = *(const float4*)(in + idx * 4);
    uint4 o;
    o.x = f2tf32(v.x); o.y = f2tf32(v.y); o.z = f2tf32(v.z); o.w = f2tf32(v.w);
    *(uint4*)(outb + idx * 4) = o;
}

// ---------------------------------------------------------------------------
// TF32 mma.sync GEMM (NT), inputs tf32-rounded.
// Block tile 256m x 128n, BK=16, 512 threads: 16 warps (4m x 4n) of 64x32.
// 3-stage cp.async pipeline, single barrier per k-iter.
// ---------------------------------------------------------------------------
#define LDA      20
#define A_BYTES  (256 * LDA * 4)    // 20480
#define B_BYTES  (128 * LDA * 4)    // 10240
#define STG      (A_BYTES + B_BYTES)
#define NSTAGE   3
#define DYN_SMEM (NSTAGE * STG)     // 92160

__global__ __launch_bounds__(512, 1) void gemm_tc(
    const float* __restrict__ A, const float* __restrict__ W,
    const float* __restrict__ bias, float* __restrict__ out,
    const int* __restrict__ sidx, int Ncols, int Kd)
{
    extern __shared__ char dyn[];
    const uint32_t sbase = sptr(dyn);

    const int t = threadIdx.x;
    const int warp = t >> 5;
    const int lane = t & 31;
    const int wm = warp & 3;        // 4 warps over M (64 rows each)
    const int wn = warp >> 2;       // 4 warps over N (32 cols each)
    const int m0 = blockIdx.y * 256;
    const int j0 = blockIdx.x * 128;

    // Fill: thread loads A rows (t>>2) and (t>>2)+128, B row (t>>2); float4 t&3.
    const int fr = t >> 2;
    const int c4 = t & 3;
    const float* Ag0 = A + (size_t)(m0 + fr)       * Kd + c4 * 4;
    const float* Ag1 = A + (size_t)(m0 + fr + 128) * Kd + c4 * 4;
    const float* Wg0 = W + (size_t)(j0 + fr)       * Kd + c4 * 4;
    const uint32_t sw0 = fr * 80 + c4 * 16;
    const uint32_t sw1 = (fr + 128) * 80 + c4 * 16;

#define ISSUE_STAGE(s, kt) do {                                   \
        uint32_t ab_ = sbase + (s) * STG;                         \
        uint32_t bb_ = ab_ + A_BYTES;                             \
        int ko_ = (kt) * 16;                                      \
        cpa16(ab_ + sw0, Ag0 + ko_);                              \
        cpa16(ab_ + sw1, Ag1 + ko_);                              \
        cpa16(bb_ + sw0, Wg0 + ko_);                              \
    } while (0)

    float acc[4][4][4];
    #pragma unroll
    for (int mt = 0; mt < 4; mt++)
        #pragma unroll
        for (int nt = 0; nt < 4; nt++)
            #pragma unroll
            for (int i = 0; i < 4; i++) acc[mt][nt][i] = 0.f;

    const int iters = Kd >> 4;

    ISSUE_STAGE(0, 0); cpa_commit();
    ISSUE_STAGE(1, 1); cpa_commit();

    const int a_roff = (lane & 7) + ((lane & 8) ? 8 : 0);
    const int a_coff = (lane & 16) ? 4 : 0;
    const int b_roff = (lane & 7) + ((lane & 16) ? 8 : 0);
    const int b_coff = (lane & 8) ? 4 : 0;

    for (int c = 0; c < iters; c++) {
        const int s = c % NSTAGE;
        cpa_wait1();
        __syncthreads();              // single barrier per iter (see analysis)
        if (c + 2 < iters) ISSUE_STAGE((c + 2) % NSTAGE, c + 2);
        cpa_commit();

        const uint32_t ab = sbase + s * STG;
        const uint32_t bb = ab + A_BYTES;
        #pragma unroll
        for (int ks = 0; ks < 16; ks += 8) {
            uint32_t bf[4][2];
            #pragma unroll
            for (int ntp = 0; ntp < 2; ntp++) {
                ldsm_x4(bf[2*ntp][0], bf[2*ntp][1], bf[2*ntp+1][0], bf[2*ntp+1][1],
                        bb + ((wn * 32 + ntp * 16 + b_roff) * LDA + ks + b_coff) * 4);
            }
            #pragma unroll
            for (int mt = 0; mt < 4; mt++) {
                uint32_t a0, a1, a2, a3;
                ldsm_x4(a0, a1, a2, a3,
                        ab + ((wm * 64 + mt * 16 + a_roff) * LDA + ks + a_coff) * 4);
                #pragma unroll
                for (int nt = 0; nt < 4; nt++)
                    mma_tf32(acc[mt][nt], a0, a1, a2, a3, bf[nt][0], bf[nt][1]);
            }
        }
    }
    __syncthreads();   // protect last-read stages before epilogue reuses nothing; cheap

    const int gr = lane >> 2;
    const int gc = lane & 3;
    #pragma unroll
    for (int mt = 0; mt < 4; mt++) {
        int m_a = m0 + wm * 64 + mt * 16 + gr;
        int m_b = m_a + 8;
        int orow_a = sidx ? sidx[m_a] : m_a;
        int orow_b = sidx ? sidx[m_b] : m_b;
        #pragma unroll
        for (int nt = 0; nt < 4; nt++) {
            int col = j0 + wn * 32 + nt * 8 + gc * 2;
            float b0 = bias[col], b1 = bias[col + 1];
            float2 v0 = make_float2(acc[mt][nt][0] + b0, acc[mt][nt][1] + b1);
            float2 v1 = make_float2(acc[mt][nt][2] + b0, acc[mt][nt][3] + b1);
            *(float2*)(out + (size_t)orow_a * Ncols + col) = v0;
            *(float2*)(out + (size_t)orow_b * Ncols + col) = v1;
        }
    }
#undef ISSUE_STAGE
}

// ---------------------------------------------------------------------------
// Attention v2 (unchanged from round 7): register softmax, 2 CTAs/SM.
// ---------------------------------------------------------------------------
#define LQ 68
#define LP 132

struct __align__(16) AttnSmem {
    uint32_t qs[128 * LQ];
    uint32_t ks[128 * LQ];
    uint32_t vt[64 * LP];
    int      cx[128], cy[128], cz[128];
    float    rp[3][RPE_MAX];
};

__global__ __launch_bounds__(256, 2) void attn_kernel(
    const float* __restrict__ qkv, const int* __restrict__ gcoord,
    const int* __restrict__ order, const float* __restrict__ rpe,
    float* __restrict__ out, int rpe_num, int pos_b)
{
    extern __shared__ char smem_raw[];
    AttnSmem& sm = *reinterpret_cast<AttnSmem*>(smem_raw);
    const int p = blockIdx.x;
    const int h = blockIdx.y;
    const int t = threadIdx.x;
    const int lane = t & 31;
    const int warp = t >> 5;

    for (int f = t; f < 2048; f += 256) {
        int i  = f >> 4;
        int dg = (f & 15) * 4;
        const float* base = qkv + (size_t)(p * 128 + i) * C3 + h * 64 + dg;
        float4 qv = *(const float4*)(base);
        float4 kv = *(const float4*)(base + 512);
        float4 vv = *(const float4*)(base + 1024);
        uint32_t* qp = &sm.qs[i * LQ + dg];
        uint32_t* kp = &sm.ks[i * LQ + dg];
        qp[0]=f2tf32(qv.x); qp[1]=f2tf32(qv.y); qp[2]=f2tf32(qv.z); qp[3]=f2tf32(qv.w);
        kp[0]=f2tf32(kv.x); kp[1]=f2tf32(kv.y); kp[2]=f2tf32(kv.z); kp[3]=f2tf32(kv.w);
        sm.vt[(dg + 0) * LP + i] = f2tf32(vv.x);
        sm.vt[(dg + 1) * LP + i] = f2tf32(vv.y);
        sm.vt[(dg + 2) * LP + i] = f2tf32(vv.z);
        sm.vt[(dg + 3) * LP + i] = f2tf32(vv.w);
    }
    if (t < 128) {
        int gi = order[p * 128 + t];
        sm.cx[t] = gcoord[gi * 3 + 0];
        sm.cy[t] = gcoord[gi * 3 + 1];
        sm.cz[t] = gcoord[gi * 3 + 2];
    }
    if (t < 3 * rpe_num) {
        sm.rp[t / rpe_num][t % rpe_num] = rpe[t * H_NUM + h];
    }
    __syncthreads();

    const int m0w = warp * 16;
    const int a_roff = (lane & 7) + ((lane & 8) ? 8 : 0);
    const int a_coff = (lane & 16) ? 4 : 0;
    const int b_roff = (lane & 7) + ((lane & 16) ? 8 : 0);
    const int b_coff = (lane & 8) ? 4 : 0;
    const int gr = lane >> 2;
    const int gc = lane & 3;

    float acc[16][4];
    #pragma unroll
    for (int nt = 0; nt < 16; nt++)
        #pragma unroll
        for (int i = 0; i < 4; i++) acc[nt][i] = 0.f;

    #pragma unroll
    for (int d0 = 0; d0 < 64; d0 += 8) {
        uint32_t a0, a1, a2, a3;
        ldsm_x4(a0, a1, a2, a3, sptr(&sm.qs[(m0w + a_roff) * LQ + d0 + a_coff]));
        #pragma unroll
        for (int ntp = 0; ntp < 8; ntp++) {
            uint32_t b0, b1, c0, c1;
            ldsm_x4(b0, b1, c0, c1, sptr(&sm.ks[(ntp * 16 + b_roff) * LQ + d0 + b_coff]));
            mma_tf32(acc[2*ntp],     a0, a1, a2, a3, b0, b1);
            mma_tf32(acc[2*ntp + 1], a0, a1, a2, a3, c0, c1);
        }
    }

    const float scale = 0.125f;
    const int i0 = m0w + gr, i1 = i0 + 8;
    const int x0 = sm.cx[i0], y0 = sm.cy[i0], z0 = sm.cz[i0];
    const int x1 = sm.cx[i1], y1 = sm.cy[i1], z1 = sm.cz[i1];
    #pragma unroll
    for (int nt = 0; nt < 16; nt++) {
        #pragma unroll
        for (int jj = 0; jj < 2; jj++) {
            int j = nt * 8 + gc * 2 + jj;
            int xj = sm.cx[j], yj = sm.cy[j], zj = sm.cz[j];
            int dx0 = min(max(x0 - xj, -pos_b), pos_b) + pos_b;
            int dy0 = min(max(y0 - yj, -pos_b), pos_b) + pos_b;
            int dz0 = min(max(z0 - zj, -pos_b), pos_b) + pos_b;
            int dx1 = min(max(x1 - xj, -pos_b), pos_b) + pos_b;
            int dy1 = min(max(y1 - yj, -pos_b), pos_b) + pos_b;
            int dz1 = min(max(z1 - zj, -pos_b), pos_b) + pos_b;
            acc[nt][jj]     = acc[nt][jj]     * scale
                            + sm.rp[0][dx0] + sm.rp[1][dy0] + sm.rp[2][dz0];
            acc[nt][jj + 2] = acc[nt][jj + 2] * scale
                            + sm.rp[0][dx1] + sm.rp[1][dy1] + sm.rp[2][dz1];
        }
    }

    float mx0 = -1e30f, mx1 = -1e30f;
    #pragma unroll
    for (int nt = 0; nt < 16; nt++) {
        mx0 = fmaxf(mx0, fmaxf(acc[nt][0], acc[nt][1]));
        mx1 = fmaxf(mx1, fmaxf(acc[nt][2], acc[nt][3]));
    }
    mx0 = fmaxf(mx0, __shfl_xor_sync(0xffffffffu, mx0, 1));
    mx0 = fmaxf(mx0, __shfl_xor_sync(0xffffffffu, mx0, 2));
    mx1 = fmaxf(mx1, __shfl_xor_sync(0xffffffffu, mx1, 1));
    mx1 = fmaxf(mx1, __shfl_xor_sync(0xffffffffu, mx1, 2));

    float s0 = 0.f, s1 = 0.f;
    #pragma unroll
    for (int nt = 0; nt < 16; nt++) {
        acc[nt][0] = __expf(acc[nt][0] - mx0);
        acc[nt][1] = __expf(acc[nt][1] - mx0);
        acc[nt][2] = __expf(acc[nt][2] - mx1);
        acc[nt][3] = __expf(acc[nt][3] - mx1);
        s0 += acc[nt][0] + acc[nt][1];
        s1 += acc[nt][2] + acc[nt][3];
    }
    s0 += __shfl_xor_sync(0xffffffffu, s0, 1);
    s0 += __shfl_xor_sync(0xffffffffu, s0, 2);
    s1 += __shfl_xor_sync(0xffffffffu, s1, 1);
    s1 += __shfl_xor_sync(0xffffffffu, s1, 2);

    float o[8][4];
    #pragma unroll
    for (int nt = 0; nt < 8; nt++)
        #pragma unroll
        for (int i = 0; i < 4; i++) o[nt][i] = 0.f;

    const int base_l = lane & ~3;
    const int src_lo = base_l | (gc >> 1);
    const int src_hi = src_lo + 2;
    const bool odd = (gc & 1);

    #pragma unroll
    for (int kg = 0; kg < 16; kg++) {
        float p00 = __shfl_sync(0xffffffffu, acc[kg][0], src_lo);
        float p01 = __shfl_sync(0xffffffffu, acc[kg][1], src_lo);
        float p02 = __shfl_sync(0xffffffffu, acc[kg][0], src_hi);
        float p03 = __shfl_sync(0xffffffffu, acc[kg][1], src_hi);
        float p10 = __shfl_sync(0xffffffffu, acc[kg][2], src_lo);
        float p11 = __shfl_sync(0xffffffffu, acc[kg][3], src_lo);
        float p12 = __shfl_sync(0xffffffffu, acc[kg][2], src_hi);
        float p13 = __shfl_sync(0xffffffffu, acc[kg][3], src_hi);
        uint32_t a0 = f2tf32(odd ? p01 : p00);
        uint32_t a1 = f2tf32(odd ? p11 : p10);
        uint32_t a2 = f2tf32(odd ? p03 : p02);
        uint32_t a3 = f2tf32(odd ? p13 : p12);
        #pragma unroll
        for (int ntp = 0; ntp < 4; ntp++) {
            uint32_t b0, b1, c0, c1;
            ldsm_x4(b0, b1, c0, c1,
                    sptr(&sm.vt[(ntp * 16 + b_roff) * LP + kg * 8 + b_coff]));
            mma_tf32(o[2*ntp],     a0, a1, a2, a3, b0, b1);
            mma_tf32(o[2*ntp + 1], a0, a1, a2, a3, c0, c1);
        }
    }

    const float inv0 = 1.f / s0;
    const float inv1 = 1.f / s1;
    #pragma unroll
    for (int nt = 0; nt < 8; nt++) {
        int col = h * 64 + nt * 8 + gc * 2;
        float2 w0, w1;
        w0.x = __uint_as_float(f2tf32(o[nt][0] * inv0));
        w0.y = __uint_as_float(f2tf32(o[nt][1] * inv0));
        w1.x = __uint_as_float(f2tf32(o[nt][2] * inv1));
        w1.y = __uint_as_float(f2tf32(o[nt][3] * inv1));
        *(float2*)(out + (size_t)(p * 128 + i0) * C_DIM + col) = w0;
        *(float2*)(out + (size_t)(p * 128 + i1) * C_DIM + col) = w1;
    }
}

// ---------------------------------------------------------------------------
extern "C" void kernel_launch(void* const* d_in, const int* in_sizes, int n_in,
                              void* d_out, int out_size)
{
    const float* feat   = (const float*)d_in[0];
    const int*   gcoord = (const int*)  d_in[1];
    const int*   order  = (const int*)  d_in[2];
    const float* qkv_w  = (const float*)d_in[4];
    const float* qkv_b  = (const float*)d_in[5];
    const float* proj_w = (const float*)d_in[6];
    const float* proj_b = (const float*)d_in[7];
    const float* rpe    = (const float*)d_in[8];
    float* out = (float*)d_out;

    int rpe_num = in_sizes[8] / (3 * H_NUM);   // 31 (ref comment is wrong)
    if (rpe_num > RPE_MAX) rpe_num = RPE_MAX;
    int pos_b = (rpe_num - 1) / 2;

    float *qkv_buf = nullptr, *ao_buf = nullptr;
    uint32_t *gath = nullptr, *w1 = nullptr, *w3 = nullptr;
    cudaGetSymbolAddress((void**)&qkv_buf, g_qkv);
    cudaGetSymbolAddress((void**)&ao_buf,  g_ao);
    cudaGetSymbolAddress((void**)&gath,    g_gath);
    cudaGetSymbolAddress((void**)&w1,      g_w1);
    cudaGetSymbolAddress((void**)&w3,      g_w3);

    cudaFuncSetAttribute(gemm_tc,
                         cudaFuncAttributeMaxDynamicSharedMemorySize, DYN_SMEM);
    cudaFuncSetAttribute(attn_kernel,
                         cudaFuncAttributeMaxDynamicSharedMemorySize,
                         (int)sizeof(AttnSmem));

    // Pre-pass
    gather_cvt<<<(N_TOT * (C_DIM / 4)) / 256, 256>>>(feat, order, gath);
    cvt_only<<<(C3 * C_DIM / 4) / 256, 256>>>(qkv_w, w1);
    cvt_only<<<(C_DIM * C_DIM / 4) / 256, 256>>>(proj_w, w3);

    // Stage 1: QKV projection
    dim3 g1(C3 / 128, N_TOT / 256);
    gemm_tc<<<g1, 512, DYN_SMEM>>>((const float*)gath, (const float*)w1,
                                   qkv_b, qkv_buf, nullptr, C3, C_DIM);

    // Stage 2: attention
    dim3 ga(P_NUM, H_NUM);
    attn_kernel<<<ga, 256, sizeof(AttnSmem)>>>(qkv_buf, gcoord, order, rpe,
                                               ao_buf, rpe_num, pos_b);

    // Stage 3: output projection + scatter
    dim3 g3(C_DIM / 128, N_TOT / 256);
    gemm_tc<<<g3, 512, DYN_SMEM>>>((const float*)ao_buf, (const float*)w3,
                                   proj_b, out, order, C_DIM, C_DIM);
}

// round 9
// speedup vs baseline: 6.9212x; 1.7915x over previous
#include <cuda_runtime.h>
#include <cuda_fp16.h>
#include <stdint.h>

#define N_TOT   131072
#define C_DIM   512
#define H_NUM   8
#define P_NUM   1024
#define C3      1536
#define RPE_MAX 33

static __device__ __half g_qkv [(size_t)N_TOT * C3];     // stage1 out (half)
static __device__ __half g_ao  [(size_t)N_TOT * C_DIM];  // attn out (half)
static __device__ __half g_gath[(size_t)N_TOT * C_DIM];  // feat[order] half
static __device__ __half g_w1  [(size_t)C3 * C_DIM];     // qkv_w half
static __device__ __half g_w3  [(size_t)C_DIM * C_DIM];  // proj_w half

// ---------------------------------------------------------------- helpers --
__device__ __forceinline__ uint32_t sptr(const void* p) {
    return (uint32_t)__cvta_generic_to_shared(p);
}
__device__ __forceinline__ void ldsm_x4(uint32_t& r0, uint32_t& r1,
                                        uint32_t& r2, uint32_t& r3, uint32_t addr) {
    asm volatile("ldmatrix.sync.aligned.m8n8.x4.shared.b16 {%0,%1,%2,%3}, [%4];"
                 : "=r"(r0), "=r"(r1), "=r"(r2), "=r"(r3) : "r"(addr));
}
__device__ __forceinline__ void mma_f16(float* d,
                                        uint32_t a0, uint32_t a1, uint32_t a2, uint32_t a3,
                                        uint32_t b0, uint32_t b1)
{
    asm volatile(
        "mma.sync.aligned.m16n8k16.row.col.f32.f16.f16.f32 "
        "{%0,%1,%2,%3}, {%4,%5,%6,%7}, {%8,%9}, {%0,%1,%2,%3};"
        : "+f"(d[0]), "+f"(d[1]), "+f"(d[2]), "+f"(d[3])
        : "r"(a0), "r"(a1), "r"(a2), "r"(a3), "r"(b0), "r"(b1));
}
__device__ __forceinline__ uint32_t pkh2(float lo, float hi) {
    __half2 h = __floats2half2_rn(lo, hi);
    return *(uint32_t*)&h;
}
__device__ __forceinline__ void cpa16(uint32_t dst, const void* src) {
    asm volatile("cp.async.cg.shared.global [%0], [%1], 16;"
                 :: "r"(dst), "l"(src) : "memory");
}
__device__ __forceinline__ void cpa_commit() {
    asm volatile("cp.async.commit_group;" ::: "memory");
}
__device__ __forceinline__ void cpa_wait1() {
    asm volatile("cp.async.wait_group 1;" ::: "memory");
}

// ---------------------------------------------------------------------------
// Pre-pass: gather + fp32->fp16 (feat[order] -> g_gath); weight cvt to fp16
// ---------------------------------------------------------------------------
__global__ __launch_bounds__(256) void gather_cvt(
    const float* __restrict__ feat, const int* __restrict__ order,
    __half* __restrict__ outb)
{
    size_t idx = (size_t)blockIdx.x * 256 + threadIdx.x;  // 8 floats each
    int m = (int)(idx >> 6);
    int c = (int)(idx & 63) << 3;
    int src = order[m];
    const float* fp = feat + (size_t)src * C_DIM + c;
    float4 v0 = *(const float4*)(fp);
    float4 v1 = *(const float4*)(fp + 4);
    __half h[8];
    h[0]=__float2half_rn(v0.x); h[1]=__float2half_rn(v0.y);
    h[2]=__float2half_rn(v0.z); h[3]=__float2half_rn(v0.w);
    h[4]=__float2half_rn(v1.x); h[5]=__float2half_rn(v1.y);
    h[6]=__float2half_rn(v1.z); h[7]=__float2half_rn(v1.w);
    *(uint4*)(outb + idx * 8) = *(uint4*)h;
}

__global__ __launch_bounds__(256) void cvt_half(
    const float* __restrict__ in, __half* __restrict__ outb)
{
    size_t idx = (size_t)blockIdx.x * 256 + threadIdx.x;
    const float* fp = in + idx * 8;
    float4 v0 = *(const float4*)(fp);
    float4 v1 = *(const float4*)(fp + 4);
    __half h[8];
    h[0]=__float2half_rn(v0.x); h[1]=__float2half_rn(v0.y);
    h[2]=__float2half_rn(v0.z); h[3]=__float2half_rn(v0.w);
    h[4]=__float2half_rn(v1.x); h[5]=__float2half_rn(v1.y);
    h[6]=__float2half_rn(v1.z); h[7]=__float2half_rn(v1.w);
    *(uint4*)(outb + idx * 8) = *(uint4*)h;
}

// ---------------------------------------------------------------------------
// FP16 mma.sync GEMM (NT), fp32 accum: out = A * W^T + bias.
// Block 256m x 128n, BK=32, 512 threads: 16 warps (4m x 4n) of 64x32.
// 3-stage cp.async pipeline. OUT_HALF: write half (stage1) or fp32+scatter.
// ---------------------------------------------------------------------------
#define ROWB     80                       // 64B data + 16B pad per row
#define A_BYTES  (256 * ROWB)             // 20480
#define B_BYTES  (128 * ROWB)             // 10240
#define STG      (A_BYTES + B_BYTES)      // 30720
#define NSTAGE   3
#define DYN_SMEM (NSTAGE * STG)           // 92160

template<int OUT_HALF>
__global__ __launch_bounds__(512, 1) void gemm_h(
    const __half* __restrict__ A, const __half* __restrict__ W,
    const float* __restrict__ bias, void* __restrict__ outv,
    const int* __restrict__ sidx, int Ncols, int Kd)
{
    extern __shared__ char dyn[];
    const uint32_t sbase = sptr(dyn);

    const int t = threadIdx.x;
    const int warp = t >> 5;
    const int lane = t & 31;
    const int wm = warp & 3;
    const int wn = warp >> 2;
    const int m0 = blockIdx.y * 256;
    const int j0 = blockIdx.x * 128;

    // Fill: thread covers 16B chunk c4 of A rows fr, fr+128 and B row fr.
    const int fr = t >> 2;
    const int c4 = t & 3;
    const __half* Ag0 = A + (size_t)(m0 + fr)       * Kd + c4 * 8;
    const __half* Ag1 = A + (size_t)(m0 + fr + 128) * Kd + c4 * 8;
    const __half* Wg0 = W + (size_t)(j0 + fr)       * Kd + c4 * 8;
    const uint32_t sw0 = fr * ROWB + c4 * 16;
    const uint32_t sw1 = (fr + 128) * ROWB + c4 * 16;

#define ISSUE_STAGE(s, kt) do {                                   \
        uint32_t ab_ = sbase + (s) * STG;                         \
        uint32_t bb_ = ab_ + A_BYTES;                             \
        int ko_ = (kt) * 32;                                      \
        cpa16(ab_ + sw0, Ag0 + ko_);                              \
        cpa16(ab_ + sw1, Ag1 + ko_);                              \
        cpa16(bb_ + sw0, Wg0 + ko_);                              \
    } while (0)

    float acc[4][4][4];
    #pragma unroll
    for (int mt = 0; mt < 4; mt++)
        #pragma unroll
        for (int nt = 0; nt < 4; nt++)
            #pragma unroll
            for (int i = 0; i < 4; i++) acc[mt][nt][i] = 0.f;

    const int iters = Kd >> 5;   // 16 for Kd=512

    ISSUE_STAGE(0, 0); cpa_commit();
    ISSUE_STAGE(1, 1); cpa_commit();

    const int a_roff = (lane & 7) + ((lane & 8) ? 8 : 0);
    const int a_cB   = (lane & 16) ? 16 : 0;
    const int b_roff = (lane & 7) + ((lane & 16) ? 8 : 0);
    const int b_cB   = (lane & 8) ? 16 : 0;

    for (int c = 0; c < iters; c++) {
        const int s = c % NSTAGE;
        cpa_wait1();
        __syncthreads();
        if (c + 2 < iters) ISSUE_STAGE((c + 2) % NSTAGE, c + 2);
        cpa_commit();

        const uint32_t ab = sbase + s * STG;
        const uint32_t bb = ab + A_BYTES;
        #pragma unroll
        for (int ks = 0; ks < 2; ks++) {            // k16 steps within BK=32
            uint32_t bf[4][2];
            #pragma unroll
            for (int ntp = 0; ntp < 2; ntp++) {
                ldsm_x4(bf[2*ntp][0], bf[2*ntp][1], bf[2*ntp+1][0], bf[2*ntp+1][1],
                        bb + (wn * 32 + ntp * 16 + b_roff) * ROWB + ks * 32 + b_cB);
            }
            #pragma unroll
            for (int mt = 0; mt < 4; mt++) {
                uint32_t a0, a1, a2, a3;
                ldsm_x4(a0, a1, a2, a3,
                        ab + (wm * 64 + mt * 16 + a_roff) * ROWB + ks * 32 + a_cB);
                #pragma unroll
                for (int nt = 0; nt < 4; nt++)
                    mma_f16(acc[mt][nt], a0, a1, a2, a3, bf[nt][0], bf[nt][1]);
            }
        }
    }
    __syncthreads();

    const int gr = lane >> 2;
    const int gc = lane & 3;
    #pragma unroll
    for (int mt = 0; mt < 4; mt++) {
        int m_a = m0 + wm * 64 + mt * 16 + gr;
        int m_b = m_a + 8;
        int orow_a = sidx ? sidx[m_a] : m_a;
        int orow_b = sidx ? sidx[m_b] : m_b;
        #pragma unroll
        for (int nt = 0; nt < 4; nt++) {
            int col = j0 + wn * 32 + nt * 8 + gc * 2;
            float b0 = bias[col], b1 = bias[col + 1];
            if (OUT_HALF) {
                __half* out = (__half*)outv;
                *(__half2*)(out + (size_t)orow_a * Ncols + col) =
                    __floats2half2_rn(acc[mt][nt][0] + b0, acc[mt][nt][1] + b1);
                *(__half2*)(out + (size_t)orow_b * Ncols + col) =
                    __floats2half2_rn(acc[mt][nt][2] + b0, acc[mt][nt][3] + b1);
            } else {
                float* out = (float*)outv;
                *(float2*)(out + (size_t)orow_a * Ncols + col) =
                    make_float2(acc[mt][nt][0] + b0, acc[mt][nt][1] + b1);
                *(float2*)(out + (size_t)orow_b * Ncols + col) =
                    make_float2(acc[mt][nt][2] + b0, acc[mt][nt][3] + b1);
            }
        }
    }
#undef ISSUE_STAGE
}

// ---------------------------------------------------------------------------
// Attention (fp16 MMA, fp32 softmax): one block per (patch, head), 8 warps.
// Register softmax; PV A-fragments packed directly from C-fragments.
// ---------------------------------------------------------------------------
#define QS0 0                      // 128 rows x 144B (64 halves + 8 pad)
#define KS0 18432
#define VT0 36864                  // 64 rows x 272B (128 halves + 8 pad)
#define CX0 54272
#define CY0 54784
#define CZ0 55296
#define RP0 55808                  // 3 x RPE_MAX floats
#define ATTN_SMEM 56320

__global__ __launch_bounds__(256, 2) void attn_kernel(
    const __half* __restrict__ qkv, const int* __restrict__ gcoord,
    const int* __restrict__ order, const float* __restrict__ rpe,
    __half* __restrict__ out, int rpe_num, int pos_b)
{
    extern __shared__ char sm[];
    const int p = blockIdx.x;
    const int h = blockIdx.y;
    const int t = threadIdx.x;
    const int lane = t & 31;
    const int warp = t >> 5;

    int* cx = (int*)(sm + CX0);
    int* cy = (int*)(sm + CY0);
    int* cz = (int*)(sm + CZ0);
    float* rp = (float*)(sm + RP0);

    // ---- fill q/k (16B copies) + v transposed ----
    for (int f = t; f < 1024; f += 256) {
        int i  = f >> 3;
        int hg = (f & 7) * 8;
        const __half* base = qkv + (size_t)(p * 128 + i) * C3 + h * 64 + hg;
        uint4 qv = *(const uint4*)(base);
        uint4 kv = *(const uint4*)(base + 512);
        uint4 vv = *(const uint4*)(base + 1024);
        *(uint4*)(sm + QS0 + i * 144 + hg * 2) = qv;
        *(uint4*)(sm + KS0 + i * 144 + hg * 2) = kv;
        const __half* vh = (const __half*)&vv;
        #pragma unroll
        for (int j = 0; j < 8; j++)
            *(__half*)(sm + VT0 + (hg + j) * 272 + i * 2) = vh[j];
    }
    if (t < 128) {
        int gi = order[p * 128 + t];
        cx[t] = gcoord[gi * 3 + 0];
        cy[t] = gcoord[gi * 3 + 1];
        cz[t] = gcoord[gi * 3 + 2];
    }
    if (t < 3 * rpe_num) {
        rp[(t / rpe_num) * RPE_MAX + (t % rpe_num)] = rpe[t * H_NUM + h];
    }
    __syncthreads();

    const int m0w = warp * 16;
    const int a_roff = (lane & 7) + ((lane & 8) ? 8 : 0);
    const int a_cB   = (lane & 16) ? 16 : 0;
    const int b_roff = (lane & 7) + ((lane & 16) ? 8 : 0);
    const int b_cB   = (lane & 8) ? 16 : 0;
    const int gr = lane >> 2;
    const int gc = lane & 3;

    // ---- QK^T ----
    float acc[16][4];
    #pragma unroll
    for (int nt = 0; nt < 16; nt++)
        #pragma unroll
        for (int i = 0; i < 4; i++) acc[nt][i] = 0.f;

    #pragma unroll
    for (int d0 = 0; d0 < 64; d0 += 16) {
        uint32_t a0, a1, a2, a3;
        ldsm_x4(a0, a1, a2, a3,
                sptr(sm + QS0 + (m0w + a_roff) * 144 + d0 * 2 + a_cB));
        #pragma unroll
        for (int ntp = 0; ntp < 8; ntp++) {
            uint32_t b0, b1, c0, c1;
            ldsm_x4(b0, b1, c0, c1,
                    sptr(sm + KS0 + (ntp * 16 + b_roff) * 144 + d0 * 2 + b_cB));
            mma_f16(acc[2*ntp],     a0, a1, a2, a3, b0, b1);
            mma_f16(acc[2*ntp + 1], a0, a1, a2, a3, c0, c1);
        }
    }

    // ---- scale + RPE bias ----
    const float scale = 0.125f;
    const int i0 = m0w + gr, i1 = i0 + 8;
    const int x0 = cx[i0], y0 = cy[i0], z0 = cz[i0];
    const int x1 = cx[i1], y1 = cy[i1], z1 = cz[i1];
    #pragma unroll
    for (int nt = 0; nt < 16; nt++) {
        #pragma unroll
        for (int jj = 0; jj < 2; jj++) {
            int j = nt * 8 + gc * 2 + jj;
            int xj = cx[j], yj = cy[j], zj = cz[j];
            int dx0 = min(max(x0 - xj, -pos_b), pos_b) + pos_b;
            int dy0 = min(max(y0 - yj, -pos_b), pos_b) + pos_b;
            int dz0 = min(max(z0 - zj, -pos_b), pos_b) + pos_b;
            int dx1 = min(max(x1 - xj, -pos_b), pos_b) + pos_b;
            int dy1 = min(max(y1 - yj, -pos_b), pos_b) + pos_b;
            int dz1 = min(max(z1 - zj, -pos_b), pos_b) + pos_b;
            acc[nt][jj]     = acc[nt][jj]     * scale
                            + rp[dx0] + rp[RPE_MAX + dy0] + rp[2*RPE_MAX + dz0];
            acc[nt][jj + 2] = acc[nt][jj + 2] * scale
                            + rp[dx1] + rp[RPE_MAX + dy1] + rp[2*RPE_MAX + dz1];
        }
    }

    // ---- register softmax ----
    float mx0 = -1e30f, mx1 = -1e30f;
    #pragma unroll
    for (int nt = 0; nt < 16; nt++) {
        mx0 = fmaxf(mx0, fmaxf(acc[nt][0], acc[nt][1]));
        mx1 = fmaxf(mx1, fmaxf(acc[nt][2], acc[nt][3]));
    }
    mx0 = fmaxf(mx0, __shfl_xor_sync(0xffffffffu, mx0, 1));
    mx0 = fmaxf(mx0, __shfl_xor_sync(0xffffffffu, mx0, 2));
    mx1 = fmaxf(mx1, __shfl_xor_sync(0xffffffffu, mx1, 1));
    mx1 = fmaxf(mx1, __shfl_xor_sync(0xffffffffu, mx1, 2));

    float s0 = 0.f, s1 = 0.f;
    #pragma unroll
    for (int nt = 0; nt < 16; nt++) {
        acc[nt][0] = __expf(acc[nt][0] - mx0);
        acc[nt][1] = __expf(acc[nt][1] - mx0);
        acc[nt][2] = __expf(acc[nt][2] - mx1);
        acc[nt][3] = __expf(acc[nt][3] - mx1);
        s0 += acc[nt][0] + acc[nt][1];
        s1 += acc[nt][2] + acc[nt][3];
    }
    s0 += __shfl_xor_sync(0xffffffffu, s0, 1);
    s0 += __shfl_xor_sync(0xffffffffu, s0, 2);
    s1 += __shfl_xor_sync(0xffffffffu, s1, 1);
    s1 += __shfl_xor_sync(0xffffffffu, s1, 2);

    // ---- PV: A fragments packed directly from C fragments (no shuffles) ----
    float o[8][4];
    #pragma unroll
    for (int nt = 0; nt < 8; nt++)
        #pragma unroll
        for (int i = 0; i < 4; i++) o[nt][i] = 0.f;

    #pragma unroll
    for (int kg = 0; kg < 8; kg++) {
        uint32_t a0 = pkh2(acc[2*kg][0],     acc[2*kg][1]);
        uint32_t a1 = pkh2(acc[2*kg][2],     acc[2*kg][3]);
        uint32_t a2 = pkh2(acc[2*kg + 1][0], acc[2*kg + 1][1]);
        uint32_t a3 = pkh2(acc[2*kg + 1][2], acc[2*kg + 1][3]);
        #pragma unroll
        for (int ntp = 0; ntp < 4; ntp++) {
            uint32_t b0, b1, c0, c1;
            ldsm_x4(b0, b1, c0, c1,
                    sptr(sm + VT0 + (ntp * 16 + b_roff) * 272 + kg * 32 + b_cB));
            mma_f16(o[2*ntp],     a0, a1, a2, a3, b0, b1);
            mma_f16(o[2*ntp + 1], a0, a1, a2, a3, c0, c1);
        }
    }

    // ---- normalize + store half ----
    const float inv0 = 1.f / s0;
    const float inv1 = 1.f / s1;
    #pragma unroll
    for (int nt = 0; nt < 8; nt++) {
        int col = h * 64 + nt * 8 + gc * 2;
        *(__half2*)(out + (size_t)(p * 128 + i0) * C_DIM + col) =
            __floats2half2_rn(o[nt][0] * inv0, o[nt][1] * inv0);
        *(__half2*)(out + (size_t)(p * 128 + i1) * C_DIM + col) =
            __floats2half2_rn(o[nt][2] * inv1, o[nt][3] * inv1);
    }
}

// ---------------------------------------------------------------------------
extern "C" void kernel_launch(void* const* d_in, const int* in_sizes, int n_in,
                              void* d_out, int out_size)
{
    const float* feat   = (const float*)d_in[0];
    const int*   gcoord = (const int*)  d_in[1];
    const int*   order  = (const int*)  d_in[2];
    const float* qkv_w  = (const float*)d_in[4];
    const float* qkv_b  = (const float*)d_in[5];
    const float* proj_w = (const float*)d_in[6];
    const float* proj_b = (const float*)d_in[7];
    const float* rpe    = (const float*)d_in[8];
    float* out = (float*)d_out;

    int rpe_num = in_sizes[8] / (3 * H_NUM);   // 31 (ref comment is wrong)
    if (rpe_num > RPE_MAX) rpe_num = RPE_MAX;
    int pos_b = (rpe_num - 1) / 2;

    __half *qkv_buf = nullptr, *ao_buf = nullptr, *gath = nullptr,
           *w1 = nullptr, *w3 = nullptr;
    cudaGetSymbolAddress((void**)&qkv_buf, g_qkv);
    cudaGetSymbolAddress((void**)&ao_buf,  g_ao);
    cudaGetSymbolAddress((void**)&gath,    g_gath);
    cudaGetSymbolAddress((void**)&w1,      g_w1);
    cudaGetSymbolAddress((void**)&w3,      g_w3);

    cudaFuncSetAttribute(gemm_h<1>,
                         cudaFuncAttributeMaxDynamicSharedMemorySize, DYN_SMEM);
    cudaFuncSetAttribute(gemm_h<0>,
                         cudaFuncAttributeMaxDynamicSharedMemorySize, DYN_SMEM);
    cudaFuncSetAttribute(attn_kernel,
                         cudaFuncAttributeMaxDynamicSharedMemorySize, ATTN_SMEM);

    // Pre-pass: gather+cvt feat, cvt weights (all to fp16)
    gather_cvt<<<(N_TOT * (C_DIM / 8)) / 256, 256>>>(feat, order, gath);
    cvt_half<<<(C3 * C_DIM / 8) / 256, 256>>>(qkv_w, w1);
    cvt_half<<<(C_DIM * C_DIM / 8) / 256, 256>>>(proj_w, w3);

    // Stage 1: QKV projection (fp16 in, half out)
    dim3 g1(C3 / 128, N_TOT / 256);
    gemm_h<1><<<g1, 512, DYN_SMEM>>>(gath, w1, qkv_b, qkv_buf, nullptr,
                                     C3, C_DIM);

    // Stage 2: attention (half in, half out)
    dim3 ga(P_NUM, H_NUM);
    attn_kernel<<<ga, 256, ATTN_SMEM>>>(qkv_buf, gcoord, order, rpe,
                                        ao_buf, rpe_num, pos_b);

    // Stage 3: output projection + scatter (half in, fp32 out)
    dim3 g3(C_DIM / 128, N_TOT / 256);
    gemm_h<0><<<g3, 512, DYN_SMEM>>>(ao_buf, w3, proj_b, out, order,
                                     C_DIM, C_DIM);
}

// round 10
// speedup vs baseline: 7.1091x; 1.0272x over previous
#include <cuda_runtime.h>
#include <cuda_fp16.h>
#include <stdint.h>

#define N_TOT   131072
#define C_DIM   512
#define H_NUM   8
#define P_NUM   1024
#define C3      1536
#define RPE_MAX 33

static __device__ __half g_qkv [(size_t)N_TOT * C3];     // stage1 out (half)
static __device__ __half g_ao  [(size_t)N_TOT * C_DIM];  // attn out (half)
static __device__ __half g_gath[(size_t)N_TOT * C_DIM];  // feat[order] half
static __device__ __half g_w1  [(size_t)C3 * C_DIM];     // qkv_w half
static __device__ __half g_w3  [(size_t)C_DIM * C_DIM];  // proj_w half

// ---------------------------------------------------------------- helpers --
__device__ __forceinline__ uint32_t sptr(const void* p) {
    return (uint32_t)__cvta_generic_to_shared(p);
}
__device__ __forceinline__ void ldsm_x4(uint32_t& r0, uint32_t& r1,
                                        uint32_t& r2, uint32_t& r3, uint32_t addr) {
    asm volatile("ldmatrix.sync.aligned.m8n8.x4.shared.b16 {%0,%1,%2,%3}, [%4];"
                 : "=r"(r0), "=r"(r1), "=r"(r2), "=r"(r3) : "r"(addr));
}
__device__ __forceinline__ void mma_f16(float* d,
                                        uint32_t a0, uint32_t a1, uint32_t a2, uint32_t a3,
                                        uint32_t b0, uint32_t b1)
{
    asm volatile(
        "mma.sync.aligned.m16n8k16.row.col.f32.f16.f16.f32 "
        "{%0,%1,%2,%3}, {%4,%5,%6,%7}, {%8,%9}, {%0,%1,%2,%3};"
        : "+f"(d[0]), "+f"(d[1]), "+f"(d[2]), "+f"(d[3])
        : "r"(a0), "r"(a1), "r"(a2), "r"(a3), "r"(b0), "r"(b1));
}
__device__ __forceinline__ uint32_t pkh2(float lo, float hi) {
    __half2 h = __floats2half2_rn(lo, hi);
    return *(uint32_t*)&h;
}
__device__ __forceinline__ void cpa16(uint32_t dst, const void* src) {
    asm volatile("cp.async.cg.shared.global [%0], [%1], 16;"
                 :: "r"(dst), "l"(src) : "memory");
}
__device__ __forceinline__ void cpa_commit() {
    asm volatile("cp.async.commit_group;" ::: "memory");
}
__device__ __forceinline__ void cpa_wait1() {
    asm volatile("cp.async.wait_group 1;" ::: "memory");
}

// ---------------------------------------------------------------------------
// Pre-pass: gather + fp32->fp16 (feat[order] -> g_gath); weight cvt to fp16
// ---------------------------------------------------------------------------
__global__ __launch_bounds__(256) void gather_cvt(
    const float* __restrict__ feat, const int* __restrict__ order,
    __half* __restrict__ outb)
{
    size_t idx = (size_t)blockIdx.x * 256 + threadIdx.x;  // 8 floats each
    int m = (int)(idx >> 6);
    int c = (int)(idx & 63) << 3;
    int src = order[m];
    const float* fp = feat + (size_t)src * C_DIM + c;
    float4 v0 = *(const float4*)(fp);
    float4 v1 = *(const float4*)(fp + 4);
    __half h[8];
    h[0]=__float2half_rn(v0.x); h[1]=__float2half_rn(v0.y);
    h[2]=__float2half_rn(v0.z); h[3]=__float2half_rn(v0.w);
    h[4]=__float2half_rn(v1.x); h[5]=__float2half_rn(v1.y);
    h[6]=__float2half_rn(v1.z); h[7]=__float2half_rn(v1.w);
    *(uint4*)(outb + idx * 8) = *(uint4*)h;
}

__global__ __launch_bounds__(256) void cvt_half(
    const float* __restrict__ in, __half* __restrict__ outb)
{
    size_t idx = (size_t)blockIdx.x * 256 + threadIdx.x;
    const float* fp = in + idx * 8;
    float4 v0 = *(const float4*)(fp);
    float4 v1 = *(const float4*)(fp + 4);
    __half h[8];
    h[0]=__float2half_rn(v0.x); h[1]=__float2half_rn(v0.y);
    h[2]=__float2half_rn(v0.z); h[3]=__float2half_rn(v0.w);
    h[4]=__float2half_rn(v1.x); h[5]=__float2half_rn(v1.y);
    h[6]=__float2half_rn(v1.z); h[7]=__float2half_rn(v1.w);
    *(uint4*)(outb + idx * 8) = *(uint4*)h;
}

// ---------------------------------------------------------------------------
// FP16 mma.sync GEMM (NT), fp32 accum: out = A * W^T + bias.
// Block 256m x 128n, BK=64, 512 threads: 16 warps (4m x 4n) of 64x32.
// 3-stage cp.async pipeline (8 iters for K=512 -> half the barrier bubbles).
// ---------------------------------------------------------------------------
#define ROWB     144                      // 128B data + 16B pad per row
#define A_BYTES  (256 * ROWB)             // 36864
#define B_BYTES  (128 * ROWB)             // 18432
#define STG      (A_BYTES + B_BYTES)      // 55296
#define NSTAGE   3
#define DYN_SMEM (NSTAGE * STG)           // 165888

template<int OUT_HALF>
__global__ __launch_bounds__(512, 1) void gemm_h(
    const __half* __restrict__ A, const __half* __restrict__ W,
    const float* __restrict__ bias, void* __restrict__ outv,
    const int* __restrict__ sidx, int Ncols, int Kd)
{
    extern __shared__ char dyn[];
    const uint32_t sbase = sptr(dyn);

    const int t = threadIdx.x;
    const int warp = t >> 5;
    const int lane = t & 31;
    const int wm = warp & 3;
    const int wn = warp >> 2;
    const int m0 = blockIdx.y * 256;
    const int j0 = blockIdx.x * 128;

    // Fill: thread covers 16B chunk c8 of rows fr (+64j). 64 halves per row.
    const int fr = t >> 3;          // 0..63
    const int c8 = t & 7;           // 0..7
    const __half* Ag0 = A + (size_t)(m0 + fr)       * Kd + c8 * 8;
    const __half* Ag1 = A + (size_t)(m0 + fr + 64)  * Kd + c8 * 8;
    const __half* Ag2 = A + (size_t)(m0 + fr + 128) * Kd + c8 * 8;
    const __half* Ag3 = A + (size_t)(m0 + fr + 192) * Kd + c8 * 8;
    const __half* Wg0 = W + (size_t)(j0 + fr)       * Kd + c8 * 8;
    const __half* Wg1 = W + (size_t)(j0 + fr + 64)  * Kd + c8 * 8;
    const uint32_t so0 = fr * ROWB + c8 * 16;
    const uint32_t so1 = (fr + 64)  * ROWB + c8 * 16;
    const uint32_t so2 = (fr + 128) * ROWB + c8 * 16;
    const uint32_t so3 = (fr + 192) * ROWB + c8 * 16;

#define ISSUE_STAGE(s, kt) do {                                   \
        uint32_t ab_ = sbase + (s) * STG;                         \
        uint32_t bb_ = ab_ + A_BYTES;                             \
        int ko_ = (kt) * 64;                                      \
        cpa16(ab_ + so0, Ag0 + ko_);                              \
        cpa16(ab_ + so1, Ag1 + ko_);                              \
        cpa16(ab_ + so2, Ag2 + ko_);                              \
        cpa16(ab_ + so3, Ag3 + ko_);                              \
        cpa16(bb_ + so0, Wg0 + ko_);                              \
        cpa16(bb_ + so1, Wg1 + ko_);                              \
    } while (0)

    float acc[4][4][4];
    #pragma unroll
    for (int mt = 0; mt < 4; mt++)
        #pragma unroll
        for (int nt = 0; nt < 4; nt++)
            #pragma unroll
            for (int i = 0; i < 4; i++) acc[mt][nt][i] = 0.f;

    const int iters = Kd >> 6;   // 8 for Kd=512

    ISSUE_STAGE(0, 0); cpa_commit();
    ISSUE_STAGE(1, 1); cpa_commit();

    const int a_roff = (lane & 7) + ((lane & 8) ? 8 : 0);
    const int a_cB   = (lane & 16) ? 16 : 0;
    const int b_roff = (lane & 7) + ((lane & 16) ? 8 : 0);
    const int b_cB   = (lane & 8) ? 16 : 0;

    for (int c = 0; c < iters; c++) {
        const int s = c % NSTAGE;
        cpa_wait1();
        __syncthreads();
        if (c + 2 < iters) ISSUE_STAGE((c + 2) % NSTAGE, c + 2);
        cpa_commit();

        const uint32_t ab = sbase + s * STG;
        const uint32_t bb = ab + A_BYTES;
        #pragma unroll
        for (int ks = 0; ks < 4; ks++) {            // 4 k16 steps within BK=64
            uint32_t bf[4][2];
            #pragma unroll
            for (int ntp = 0; ntp < 2; ntp++) {
                ldsm_x4(bf[2*ntp][0], bf[2*ntp][1], bf[2*ntp+1][0], bf[2*ntp+1][1],
                        bb + (wn * 32 + ntp * 16 + b_roff) * ROWB + ks * 32 + b_cB);
            }
            #pragma unroll
            for (int mt = 0; mt < 4; mt++) {
                uint32_t a0, a1, a2, a3;
                ldsm_x4(a0, a1, a2, a3,
                        ab + (wm * 64 + mt * 16 + a_roff) * ROWB + ks * 32 + a_cB);
                #pragma unroll
                for (int nt = 0; nt < 4; nt++)
                    mma_f16(acc[mt][nt], a0, a1, a2, a3, bf[nt][0], bf[nt][1]);
            }
        }
    }
    __syncthreads();

    const int gr = lane >> 2;
    const int gc = lane & 3;
    #pragma unroll
    for (int mt = 0; mt < 4; mt++) {
        int m_a = m0 + wm * 64 + mt * 16 + gr;
        int m_b = m_a + 8;
        int orow_a = sidx ? sidx[m_a] : m_a;
        int orow_b = sidx ? sidx[m_b] : m_b;
        #pragma unroll
        for (int nt = 0; nt < 4; nt++) {
            int col = j0 + wn * 32 + nt * 8 + gc * 2;
            float b0 = bias[col], b1 = bias[col + 1];
            if (OUT_HALF) {
                __half* out = (__half*)outv;
                *(__half2*)(out + (size_t)orow_a * Ncols + col) =
                    __floats2half2_rn(acc[mt][nt][0] + b0, acc[mt][nt][1] + b1);
                *(__half2*)(out + (size_t)orow_b * Ncols + col) =
                    __floats2half2_rn(acc[mt][nt][2] + b0, acc[mt][nt][3] + b1);
            } else {
                float* out = (float*)outv;
                *(float2*)(out + (size_t)orow_a * Ncols + col) =
                    make_float2(acc[mt][nt][0] + b0, acc[mt][nt][1] + b1);
                *(float2*)(out + (size_t)orow_b * Ncols + col) =
                    make_float2(acc[mt][nt][2] + b0, acc[mt][nt][3] + b1);
            }
        }
    }
#undef ISSUE_STAGE
}

// ---------------------------------------------------------------------------
// Attention (fp16 MMA, fp32 softmax): one block per (patch, head), 8 warps.
// Register softmax; PV A-fragments packed directly from C-fragments.
// ---------------------------------------------------------------------------
#define QS0 0                      // 128 rows x 144B (64 halves + 8 pad)
#define KS0 18432
#define VT0 36864                  // 64 rows x 272B (128 halves + 8 pad)
#define CX0 54272
#define CY0 54784
#define CZ0 55296
#define RP0 55808                  // 3 x RPE_MAX floats
#define ATTN_SMEM 56320

__global__ __launch_bounds__(256, 2) void attn_kernel(
    const __half* __restrict__ qkv, const int* __restrict__ gcoord,
    const int* __restrict__ order, const float* __restrict__ rpe,
    __half* __restrict__ out, int rpe_num, int pos_b)
{
    extern __shared__ char sm[];
    const int p = blockIdx.x;
    const int h = blockIdx.y;
    const int t = threadIdx.x;
    const int lane = t & 31;
    const int warp = t >> 5;

    int* cx = (int*)(sm + CX0);
    int* cy = (int*)(sm + CY0);
    int* cz = (int*)(sm + CZ0);
    float* rp = (float*)(sm + RP0);

    for (int f = t; f < 1024; f += 256) {
        int i  = f >> 3;
        int hg = (f & 7) * 8;
        const __half* base = qkv + (size_t)(p * 128 + i) * C3 + h * 64 + hg;
        uint4 qv = *(const uint4*)(base);
        uint4 kv = *(const uint4*)(base + 512);
        uint4 vv = *(const uint4*)(base + 1024);
        *(uint4*)(sm + QS0 + i * 144 + hg * 2) = qv;
        *(uint4*)(sm + KS0 + i * 144 + hg * 2) = kv;
        const __half* vh = (const __half*)&vv;
        #pragma unroll
        for (int j = 0; j < 8; j++)
            *(__half*)(sm + VT0 + (hg + j) * 272 + i * 2) = vh[j];
    }
    if (t < 128) {
        int gi = order[p * 128 + t];
        cx[t] = gcoord[gi * 3 + 0];
        cy[t] = gcoord[gi * 3 + 1];
        cz[t] = gcoord[gi * 3 + 2];
    }
    if (t < 3 * rpe_num) {
        rp[(t / rpe_num) * RPE_MAX + (t % rpe_num)] = rpe[t * H_NUM + h];
    }
    __syncthreads();

    const int m0w = warp * 16;
    const int a_roff = (lane & 7) + ((lane & 8) ? 8 : 0);
    const int a_cB   = (lane & 16) ? 16 : 0;
    const int b_roff = (lane & 7) + ((lane & 16) ? 8 : 0);
    const int b_cB   = (lane & 8) ? 16 : 0;
    const int gr = lane >> 2;
    const int gc = lane & 3;

    float acc[16][4];
    #pragma unroll
    for (int nt = 0; nt < 16; nt++)
        #pragma unroll
        for (int i = 0; i < 4; i++) acc[nt][i] = 0.f;

    #pragma unroll
    for (int d0 = 0; d0 < 64; d0 += 16) {
        uint32_t a0, a1, a2, a3;
        ldsm_x4(a0, a1, a2, a3,
                sptr(sm + QS0 + (m0w + a_roff) * 144 + d0 * 2 + a_cB));
        #pragma unroll
        for (int ntp = 0; ntp < 8; ntp++) {
            uint32_t b0, b1, c0, c1;
            ldsm_x4(b0, b1, c0, c1,
                    sptr(sm + KS0 + (ntp * 16 + b_roff) * 144 + d0 * 2 + b_cB));
            mma_f16(acc[2*ntp],     a0, a1, a2, a3, b0, b1);
            mma_f16(acc[2*ntp + 1], a0, a1, a2, a3, c0, c1);
        }
    }

    const float scale = 0.125f;
    const int i0 = m0w + gr, i1 = i0 + 8;
    const int x0 = cx[i0], y0 = cy[i0], z0 = cz[i0];
    const int x1 = cx[i1], y1 = cy[i1], z1 = cz[i1];
    #pragma unroll
    for (int nt = 0; nt < 16; nt++) {
        #pragma unroll
        for (int jj = 0; jj < 2; jj++) {
            int j = nt * 8 + gc * 2 + jj;
            int xj = cx[j], yj = cy[j], zj = cz[j];
            int dx0 = min(max(x0 - xj, -pos_b), pos_b) + pos_b;
            int dy0 = min(max(y0 - yj, -pos_b), pos_b) + pos_b;
            int dz0 = min(max(z0 - zj, -pos_b), pos_b) + pos_b;
            int dx1 = min(max(x1 - xj, -pos_b), pos_b) + pos_b;
            int dy1 = min(max(y1 - yj, -pos_b), pos_b) + pos_b;
            int dz1 = min(max(z1 - zj, -pos_b), pos_b) + pos_b;
            acc[nt][jj]     = acc[nt][jj]     * scale
                            + rp[dx0] + rp[RPE_MAX + dy0] + rp[2*RPE_MAX + dz0];
            acc[nt][jj + 2] = acc[nt][jj + 2] * scale
                            + rp[dx1] + rp[RPE_MAX + dy1] + rp[2*RPE_MAX + dz1];
        }
    }

    float mx0 = -1e30f, mx1 = -1e30f;
    #pragma unroll
    for (int nt = 0; nt < 16; nt++) {
        mx0 = fmaxf(mx0, fmaxf(acc[nt][0], acc[nt][1]));
        mx1 = fmaxf(mx1, fmaxf(acc[nt][2], acc[nt][3]));
    }
    mx0 = fmaxf(mx0, __shfl_xor_sync(0xffffffffu, mx0, 1));
    mx0 = fmaxf(mx0, __shfl_xor_sync(0xffffffffu, mx0, 2));
    mx1 = fmaxf(mx1, __shfl_xor_sync(0xffffffffu, mx1, 1));
    mx1 = fmaxf(mx1, __shfl_xor_sync(0xffffffffu, mx1, 2));

    float s0 = 0.f, s1 = 0.f;
    #pragma unroll
    for (int nt = 0; nt < 16; nt++) {
        acc[nt][0] = __expf(acc[nt][0] - mx0);
        acc[nt][1] = __expf(acc[nt][1] - mx0);
        acc[nt][2] = __expf(acc[nt][2] - mx1);
        acc[nt][3] = __expf(acc[nt][3] - mx1);
        s0 += acc[nt][0] + acc[nt][1];
        s1 += acc[nt][2] + acc[nt][3];
    }
    s0 += __shfl_xor_sync(0xffffffffu, s0, 1);
    s0 += __shfl_xor_sync(0xffffffffu, s0, 2);
    s1 += __shfl_xor_sync(0xffffffffu, s1, 1);
    s1 += __shfl_xor_sync(0xffffffffu, s1, 2);

    float o[8][4];
    #pragma unroll
    for (int nt = 0; nt < 8; nt++)
        #pragma unroll
        for (int i = 0; i < 4; i++) o[nt][i] = 0.f;

    #pragma unroll
    for (int kg = 0; kg < 8; kg++) {
        uint32_t a0 = pkh2(acc[2*kg][0],     acc[2*kg][1]);
        uint32_t a1 = pkh2(acc[2*kg][2],     acc[2*kg][3]);
        uint32_t a2 = pkh2(acc[2*kg + 1][0], acc[2*kg + 1][1]);
        uint32_t a3 = pkh2(acc[2*kg + 1][2], acc[2*kg + 1][3]);
        #pragma unroll
        for (int ntp = 0; ntp < 4; ntp++) {
            uint32_t b0, b1, c0, c1;
            ldsm_x4(b0, b1, c0, c1,
                    sptr(sm + VT0 + (ntp * 16 + b_roff) * 272 + kg * 32 + b_cB));
            mma_f16(o[2*ntp],     a0, a1, a2, a3, b0, b1);
            mma_f16(o[2*ntp + 1], a0, a1, a2, a3, c0, c1);
        }
    }

    const float inv0 = 1.f / s0;
    const float inv1 = 1.f / s1;
    #pragma unroll
    for (int nt = 0; nt < 8; nt++) {
        int col = h * 64 + nt * 8 + gc * 2;
        *(__half2*)(out + (size_t)(p * 128 + i0) * C_DIM + col) =
            __floats2half2_rn(o[nt][0] * inv0, o[nt][1] * inv0);
        *(__half2*)(out + (size_t)(p * 128 + i1) * C_DIM + col) =
            __floats2half2_rn(o[nt][2] * inv1, o[nt][3] * inv1);
    }
}

// ---------------------------------------------------------------------------
extern "C" void kernel_launch(void* const* d_in, const int* in_sizes, int n_in,
                              void* d_out, int out_size)
{
    const float* feat   = (const float*)d_in[0];
    const int*   gcoord = (const int*)  d_in[1];
    const int*   order  = (const int*)  d_in[2];
    const float* qkv_w  = (const float*)d_in[4];
    const float* qkv_b  = (const float*)d_in[5];
    const float* proj_w = (const float*)d_in[6];
    const float* proj_b = (const float*)d_in[7];
    const float* rpe    = (const float*)d_in[8];
    float* out = (float*)d_out;

    int rpe_num = in_sizes[8] / (3 * H_NUM);   // 31 (ref comment is wrong)
    if (rpe_num > RPE_MAX) rpe_num = RPE_MAX;
    int pos_b = (rpe_num - 1) / 2;

    __half *qkv_buf = nullptr, *ao_buf = nullptr, *gath = nullptr,
           *w1 = nullptr, *w3 = nullptr;
    cudaGetSymbolAddress((void**)&qkv_buf, g_qkv);
    cudaGetSymbolAddress((void**)&ao_buf,  g_ao);
    cudaGetSymbolAddress((void**)&gath,    g_gath);
    cudaGetSymbolAddress((void**)&w1,      g_w1);
    cudaGetSymbolAddress((void**)&w3,      g_w3);

    cudaFuncSetAttribute(gemm_h<1>,
                         cudaFuncAttributeMaxDynamicSharedMemorySize, DYN_SMEM);
    cudaFuncSetAttribute(gemm_h<0>,
                         cudaFuncAttributeMaxDynamicSharedMemorySize, DYN_SMEM);
    cudaFuncSetAttribute(attn_kernel,
                         cudaFuncAttributeMaxDynamicSharedMemorySize, ATTN_SMEM);

    // Pre-pass: gather+cvt feat, cvt weights (all to fp16)
    gather_cvt<<<(N_TOT * (C_DIM / 8)) / 256, 256>>>(feat, order, gath);
    cvt_half<<<(C3 * C_DIM / 8) / 256, 256>>>(qkv_w, w1);
    cvt_half<<<(C_DIM * C_DIM / 8) / 256, 256>>>(proj_w, w3);

    // Stage 1: QKV projection (fp16 in, half out)
    dim3 g1(C3 / 128, N_TOT / 256);
    gemm_h<1><<<g1, 512, DYN_SMEM>>>(gath, w1, qkv_b, qkv_buf, nullptr,
                                     C3, C_DIM);

    // Stage 2: attention (half in, half out)
    dim3 ga(P_NUM, H_NUM);
    attn_kernel<<<ga, 256, ATTN_SMEM>>>(qkv_buf, gcoord, order, rpe,
                                        ao_buf, rpe_num, pos_b);

    // Stage 3: output projection + scatter (half in, fp32 out)
    dim3 g3(C_DIM / 128, N_TOT / 256);
    gemm_h<0><<<g3, 512, DYN_SMEM>>>(ao_buf, w3, proj_b, out, order,
                                     C_DIM, C_DIM);
}